// round 9
// baseline (speedup 1.0000x reference)
#include <cuda_runtime.h>
#include <cstdint>

#define EMBED 1024
#define NHEADS 16
#define HDIM 64
#define BATCH 4
#define SEQ 2048
#define MTOT (BATCH * SEQ)   // 8192

// Scratch (static device globals: allowed; no runtime allocation)
__device__ float g_q [(size_t)MTOT * EMBED];
__device__ float g_k [(size_t)MTOT * EMBED];
__device__ float g_v [(size_t)MTOT * EMBED];
__device__ float g_o [(size_t)MTOT * EMBED];
__device__ float g_xr[(size_t)MTOT * EMBED];
__device__ float g_wt[(size_t)3 * EMBED * EMBED];   // [Wq;Wk;Wv] transposed [N][K]
__device__ float g_wo[(size_t)EMBED * EMBED];       // Wo transposed [N][K]
__device__ float g_bc[3 * EMBED];                   // concat bias (q scaled)

__device__ __forceinline__ float rna(float x) {
    float r;
    asm("cvt.rna.tf32.f32 %0, %1;" : "=f"(r) : "f"(x));
    return r;
}
__device__ __forceinline__ uint32_t fbits(float x) { return __float_as_uint(x); }

__device__ __forceinline__ void mma_tf32(float c[4], const uint32_t a[4],
                                         const uint32_t b[2]) {
    asm volatile(
        "mma.sync.aligned.m16n8k8.row.col.f32.tf32.tf32.f32 "
        "{%0,%1,%2,%3}, {%4,%5,%6,%7}, {%8,%9}, {%0,%1,%2,%3};"
        : "+f"(c[0]), "+f"(c[1]), "+f"(c[2]), "+f"(c[3])
        : "r"(a[0]), "r"(a[1]), "r"(a[2]), "r"(a[3]), "r"(b[0]), "r"(b[1]));
}

__device__ __forceinline__ void cp16(void* dst_smem, const void* src) {
    uint32_t d = (uint32_t)__cvta_generic_to_shared(dst_smem);
    asm volatile("cp.async.cg.shared.global [%0], [%1], 16;" :: "r"(d), "l"(src));
}
#define CP_COMMIT() asm volatile("cp.async.commit_group;")
#define CP_WAIT0()  asm volatile("cp.async.wait_group 0;" ::: "memory")

__device__ __forceinline__ uint32_t smem_u32(const void* p) {
    return (uint32_t)__cvta_generic_to_shared(p);
}
__device__ __forceinline__ float lds32(uint32_t a) {
    float r;
    asm volatile("ld.shared.f32 %0, [%1];" : "=f"(r) : "r"(a));
    return r;
}
__device__ __forceinline__ float2 lds64(uint32_t a) {
    float2 r;
    asm volatile("ld.shared.v2.f32 {%0, %1}, [%2];" : "=f"(r.x), "=f"(r.y) : "r"(a));
    return r;
}
__device__ __forceinline__ void sts64(uint32_t a, float x, float y) {
    asm volatile("st.shared.v2.f32 [%0], {%1, %2};" :: "r"(a), "f"(x), "f"(y));
}

// ---------------------------------------------------------------------------
// elementwise rna (for x)
// ---------------------------------------------------------------------------
__global__ void preround(const float* __restrict__ s, float* __restrict__ d,
                         float sc, int n4)
{
    int i = blockIdx.x * 256 + threadIdx.x;
    if (i < n4) {
        float4 v = ((const float4*)s)[i];
        v.x = rna(v.x * sc); v.y = rna(v.y * sc);
        v.z = rna(v.z * sc); v.w = rna(v.w * sc);
        ((float4*)d)[i] = v;
    }
}

// ---------------------------------------------------------------------------
// all 4 weight transposes in one launch (z picks matrix); Wq folded * 1/8
// ---------------------------------------------------------------------------
__global__ __launch_bounds__(256) void transpose_all(
    const float* __restrict__ Wq, const float* __restrict__ Wk,
    const float* __restrict__ Wv, const float* __restrict__ Wo,
    float* __restrict__ wt, float* __restrict__ wo)
{
    __shared__ float tl[32][33];
    const int z = blockIdx.z;
    const float* src = (z == 0) ? Wq : (z == 1) ? Wk : (z == 2) ? Wv : Wo;
    float* dst = (z == 3) ? wo : wt + (size_t)z * EMBED * EMBED;
    const float sc = (z == 0) ? 0.125f : 1.0f;

    const int tx = threadIdx.x & 31, ty = threadIdx.x >> 5;  // 32 x 8
    const int x0 = blockIdx.x * 32, y0 = blockIdx.y * 32;
    #pragma unroll
    for (int j = 0; j < 32; j += 8)
        tl[ty + j][tx] = rna(src[(size_t)(y0 + ty + j) * EMBED + x0 + tx] * sc);
    __syncthreads();
    #pragma unroll
    for (int j = 0; j < 32; j += 8)
        dst[(size_t)(x0 + ty + j) * EMBED + y0 + tx] = tl[tx][ty + j];
}

// bias concat: bc[0:1024)=bq*0.125, [1024:2048)=bk, [2048:3072)=bv
__global__ void bias_cat(const float* __restrict__ bq, const float* __restrict__ bk,
                         const float* __restrict__ bv, float* __restrict__ bc)
{
    int i = blockIdx.x * 256 + threadIdx.x;
    if (i < EMBED)          bc[i] = bq[i] * 0.125f;
    else if (i < 2 * EMBED) bc[i] = bk[i - EMBED];
    else if (i < 3 * EMBED) bc[i] = bv[i - 2 * EMBED];
}

// ---------------------------------------------------------------------------
// tf32 mma.sync GEMM, k-permuted fragments, immediate-offset LDS.
// Block 128x128, 8 warps (4M x 2N), warp tile 32x64, BK=32, 2-stage cp.async,
// ONE barrier per iteration, 2 CTAs/SM.
// smem: As[2][128][40] + Bs[2][128][40] = 81920 B
// ---------------------------------------------------------------------------
#define GPAD 40
#define GTILEB (128 * GPAD * 4)
#define GEMM_SMEM (2 * 2 * 128 * GPAD * 4)

__global__ __launch_bounds__(256, 2) void gemm_big(
    const float* __restrict__ A, const float* __restrict__ BT,
    const float* __restrict__ bias, float* __restrict__ D0,
    float* __restrict__ D1, float* __restrict__ D2, int round_out)
{
    extern __shared__ float sh[];
    float* As = sh;                      // [2][128][40]
    float* Bs = sh + 2 * 128 * GPAD;     // [2][128][40]

    const int t = threadIdx.x;
    const int lane = t & 31, warp = t >> 5;
    const int g = lane >> 2, e = lane & 3;
    const int m0 = (warp & 3) * 32, n0 = (warp >> 2) * 64;

    const int row0 = blockIdx.y * 128;
    const int bx = blockIdx.x;
    const int id = bx >> 3;                       // which output matrix
    const int col0 = (bx & 7) * 128;              // col within matrix
    float* D = (id == 0) ? D0 : (id == 1) ? D1 : D2;

    // loaders: tiles staged [row][k]; thread covers (row = t>>3 (+32p), k=(t&7)*4)
    const int lr = t >> 3, lk = (t & 7) * 4;
    const float* Ab = A  + (size_t)(row0 + lr) * EMBED + lk;
    const float* Bb = BT + (size_t)(bx * 128 + lr) * EMBED + lk;

    // fragment base addresses (shared space), buffer 0
    const uint32_t aB = smem_u32(As) + (uint32_t)((m0 + g) * GPAD + 2 * e) * 4;
    const uint32_t bB = smem_u32(Bs) + (uint32_t)((n0 + g) * GPAD + 2 * e) * 4;

    #define GREFILL(k0, buf) do {                                              \
        float* sA = As + (buf) * 128 * GPAD;                                   \
        float* sB = Bs + (buf) * 128 * GPAD;                                   \
        _Pragma("unroll")                                                      \
        for (int p = 0; p < 4; ++p) {                                          \
            cp16(&sA[(lr + 32 * p) * GPAD + lk], Ab + (size_t)(32 * p) * EMBED + (k0)); \
            cp16(&sB[(lr + 32 * p) * GPAD + lk], Bb + (size_t)(32 * p) * EMBED + (k0)); \
        }                                                                      \
        CP_COMMIT();                                                           \
    } while (0)

    GREFILL(0, 0);

    float acc[2][8][4] = {};
    const int NIT = EMBED / 32;

    for (int it = 0; it < NIT; ++it) {
        CP_WAIT0();
        __syncthreads();    // also orders: all readers done with buf (it&1)
        if (it + 1 < NIT) GREFILL((it + 1) * 32, (it + 1) & 1);

        const uint32_t aA = aB + (it & 1) * GTILEB;
        const uint32_t bA = bB + (it & 1) * GTILEB;

        #pragma unroll
        for (int ks = 0; ks < 4; ++ks) {
            uint32_t a[2][4];
            #pragma unroll
            for (int mt = 0; mt < 2; ++mt) {
                float2 p0 = lds64(aA + mt * (16 * GPAD * 4) + ks * 32);
                float2 p1 = lds64(aA + mt * (16 * GPAD * 4) + 8 * GPAD * 4 + ks * 32);
                a[mt][0] = fbits(p0.x); a[mt][2] = fbits(p0.y);
                a[mt][1] = fbits(p1.x); a[mt][3] = fbits(p1.y);
            }
            #pragma unroll
            for (int n = 0; n < 8; ++n) {
                float2 q = lds64(bA + n * (8 * GPAD * 4) + ks * 32);
                uint32_t b[2] = {fbits(q.x), fbits(q.y)};
                mma_tf32(acc[0][n], a[0], b);
                mma_tf32(acc[1][n], a[1], b);
            }
        }
        // no bottom barrier: next iteration's top barrier provides the guard
    }

    // epilogue
    #pragma unroll
    for (int mt = 0; mt < 2; ++mt) {
        const int r = row0 + m0 + mt * 16 + g;
        #pragma unroll
        for (int n = 0; n < 8; ++n) {
            const int cl = col0 + n0 + n * 8 + 2 * e;         // col in matrix
            const int cb = bx * 128 + n0 + n * 8 + 2 * e;     // col in bias buf
            const float b0 = bias[cb], b1 = bias[cb + 1];
            float v00 = acc[mt][n][0] + b0, v01 = acc[mt][n][1] + b1;
            float v10 = acc[mt][n][2] + b0, v11 = acc[mt][n][3] + b1;
            if (round_out) { v00 = rna(v00); v01 = rna(v01);
                             v10 = rna(v10); v11 = rna(v11); }
            *(float2*)&D[(size_t)r * EMBED + cl]       = make_float2(v00, v01);
            *(float2*)&D[(size_t)(r + 8) * EMBED + cl] = make_float2(v10, v11);
        }
    }
}

// ---------------------------------------------------------------------------
// Flash attention v5: Q-block 128 rows, 8 warps x 16 rows, Bc=64,
// 2-stage cp.async K/V, 2 CTAs/SM, immediate-offset LDS, permuted S-mma.
// smem: Ks[2][64][72] Vs[2][64][72] Ps[128][68] = 108544 B
// ---------------------------------------------------------------------------
#define KPAD 72
#define VPAD 72
#define PPAD 68
#define FKS_OFF 0
#define FVS_OFF (2 * 64 * KPAD)
#define FPS_OFF (FVS_OFF + 2 * 64 * VPAD)
#define FLASH_SMEM ((FPS_OFF + 128 * PPAD) * 4)

__global__ __launch_bounds__(256, 2) void flash_v5(
    const float* __restrict__ q, const float* __restrict__ k,
    const float* __restrict__ v, float* __restrict__ o)
{
    extern __shared__ float shf[];
    float* Ks = shf + FKS_OFF;
    float* Vs = shf + FVS_OFF;
    float* Ps = shf + FPS_OFF;

    const int t = threadIdx.x;
    const int lane = t & 31, warp = t >> 5;
    const int g = lane >> 2, e = lane & 3;
    const int m0 = warp * 16;

    const int bh = blockIdx.x;
    const int b = bh >> 4, h = bh & 15;
    const int qrow0 = blockIdx.y * 128;
    const size_t base = ((size_t)b * SEQ) * EMBED + (size_t)h * HDIM;

    const int lkey = t >> 4;          // 0..15
    const int lq4  = (t & 15) * 4;    // 0..60

    // prefetch K/V tile 0 into buf 0
    #pragma unroll
    for (int i = 0; i < 4; ++i) {
        const int key = lkey + 16 * i;
        cp16(&Ks[key * KPAD + lq4], k + base + (size_t)key * EMBED + lq4);
        cp16(&Vs[key * VPAD + lq4], v + base + (size_t)key * EMBED + lq4);
    }
    CP_COMMIT();

    // stage Q (128x64) into Ps, then hoist PERMUTED fragments to registers
    #pragma unroll
    for (int i = 0; i < 8; ++i) {
        const int row = lkey + 16 * i;
        *(float4*)&Ps[row * PPAD + lq4] =
            *(const float4*)(q + base + (size_t)(qrow0 + row) * EMBED + lq4);
    }
    __syncthreads();
    uint32_t qa[8][4];
    #pragma unroll
    for (int ks = 0; ks < 8; ++ks) {
        const int kp = ks * 8 + 2 * e;
        float2 p0 = *(const float2*)&Ps[(m0 + g) * PPAD + kp];
        float2 p1 = *(const float2*)&Ps[(m0 + g + 8) * PPAD + kp];
        qa[ks][0] = fbits(p0.x); qa[ks][2] = fbits(p0.y);
        qa[ks][1] = fbits(p1.x); qa[ks][3] = fbits(p1.y);
    }

    // fragment base addresses (shared space)
    const uint32_t kB = smem_u32(Ks) + (uint32_t)(g * KPAD + 2 * e) * 4;
    const uint32_t vB = smem_u32(Vs) + (uint32_t)(e * VPAD + g) * 4;
    const uint32_t pW = smem_u32(Ps) + (uint32_t)((m0 + g) * PPAD + 2 * e) * 4;  // P write
    const uint32_t pR = smem_u32(Ps) + (uint32_t)((m0 + g) * PPAD + e) * 4;      // P read

    float o_[8][4] = {};
    float mrow[2] = {-1e30f, -1e30f}, lrow[2] = {0.f, 0.f};

    const int NIT = SEQ / 64;
    CP_WAIT0();
    __syncthreads();

    for (int it = 0; it < NIT; ++it) {
        const int bf = it & 1;
        if (it + 1 < NIT) {
            const int nb = bf ^ 1;
            const int kt = (it + 1) * 64;
            #pragma unroll
            for (int i = 0; i < 4; ++i) {
                const int key = lkey + 16 * i;
                cp16(&Ks[nb * 64 * KPAD + key * KPAD + lq4],
                     k + base + (size_t)(kt + key) * EMBED + lq4);
                cp16(&Vs[nb * 64 * VPAD + key * VPAD + lq4],
                     v + base + (size_t)(kt + key) * EMBED + lq4);
            }
            CP_COMMIT();
        }
        const uint32_t kA = kB + bf * (64 * KPAD * 4);
        const uint32_t vA = vB + bf * (64 * VPAD * 4);

        // S = Q * K^T : permuted k-lanes, K frags via LDS.64 (immediate offsets)
        float s[8][4] = {};
        #pragma unroll
        for (int ks = 0; ks < 8; ++ks) {
            #pragma unroll
            for (int n = 0; n < 8; ++n) {
                float2 kk = lds64(kA + n * (8 * KPAD * 4) + ks * 32);
                uint32_t bb[2] = {fbits(kk.x), fbits(kk.y)};
                mma_tf32(s[n], qa[ks], bb);
            }
        }

        // online softmax per row-half
        #pragma unroll
        for (int hh = 0; hh < 2; ++hh) {
            const int ci = hh * 2;
            float mx = -1e30f;
            #pragma unroll
            for (int n = 0; n < 8; ++n)
                mx = fmaxf(mx, fmaxf(s[n][ci], s[n][ci + 1]));
            mx = fmaxf(mx, __shfl_xor_sync(0xffffffffu, mx, 1));
            mx = fmaxf(mx, __shfl_xor_sync(0xffffffffu, mx, 2));
            const float mn = fmaxf(mrow[hh], mx);
            const float al = __expf(mrow[hh] - mn);
            mrow[hh] = mn;
            float sum = 0.f;
            #pragma unroll
            for (int n = 0; n < 8; ++n) {
                const float p0 = __expf(s[n][ci] - mn);
                const float p1 = __expf(s[n][ci + 1] - mn);
                s[n][ci] = p0; s[n][ci + 1] = p1;
                sum += p0 + p1;
            }
            sum += __shfl_xor_sync(0xffffffffu, sum, 1);
            sum += __shfl_xor_sync(0xffffffffu, sum, 2);
            lrow[hh] = lrow[hh] * al + sum;
            if (al != 1.0f) {
                #pragma unroll
                for (int n = 0; n < 8; ++n) { o_[n][ci] *= al; o_[n][ci + 1] *= al; }
            }
            #pragma unroll
            for (int n = 0; n < 8; ++n)
                sts64(pW + hh * (8 * PPAD * 4) + n * 32,
                      rna(s[n][ci]), rna(s[n][ci + 1]));
        }
        __syncwarp();   // Ps rows are per-warp private

        // O += P * V  (standard k-order, immediate-offset LDS)
        #pragma unroll
        for (int ks = 0; ks < 8; ++ks) {
            uint32_t a[4];
            a[0] = fbits(lds32(pR + ks * 32));
            a[1] = fbits(lds32(pR + 8 * PPAD * 4 + ks * 32));
            a[2] = fbits(lds32(pR + 16 + ks * 32));
            a[3] = fbits(lds32(pR + 8 * PPAD * 4 + 16 + ks * 32));
            #pragma unroll
            for (int n = 0; n < 8; ++n) {
                uint32_t bb[2];
                bb[0] = fbits(lds32(vA + ks * (8 * VPAD * 4) + n * 32));
                bb[1] = fbits(lds32(vA + ks * (8 * VPAD * 4) + 4 * VPAD * 4 + n * 32));
                mma_tf32(o_[n], a, bb);
            }
        }

        CP_WAIT0();
        __syncthreads();   // next tile landed; all readers done with bf
    }

    // epilogue: O /= l, rna, write to [B*S, EMBED] at head offset
    #pragma unroll
    for (int hh = 0; hh < 2; ++hh) {
        const float inv = 1.0f / lrow[hh];
        const int row = qrow0 + m0 + g + 8 * hh;
        const int ci = hh * 2;
        #pragma unroll
        for (int n = 0; n < 8; ++n) {
            *(float2*)(o + base + (size_t)row * EMBED + n * 8 + 2 * e) =
                make_float2(rna(o_[n][ci] * inv), rna(o_[n][ci + 1] * inv));
        }
    }
}

// ---------------------------------------------------------------------------
extern "C" void kernel_launch(void* const* d_in, const int* in_sizes, int n_in,
                              void* d_out, int out_size)
{
    const float* x  = (const float*)d_in[0];
    const float* Wq = (const float*)d_in[1];
    const float* bq = (const float*)d_in[2];
    const float* Wk = (const float*)d_in[3];
    const float* bk = (const float*)d_in[4];
    const float* Wv = (const float*)d_in[5];
    const float* bv = (const float*)d_in[6];
    const float* Wo = (const float*)d_in[7];
    const float* bo = (const float*)d_in[8];
    float* out = (float*)d_out;

    float *q, *k, *v, *oa, *xr, *wt, *wo, *bc;
    cudaGetSymbolAddress((void**)&q,  g_q);
    cudaGetSymbolAddress((void**)&k,  g_k);
    cudaGetSymbolAddress((void**)&v,  g_v);
    cudaGetSymbolAddress((void**)&oa, g_o);
    cudaGetSymbolAddress((void**)&xr, g_xr);
    cudaGetSymbolAddress((void**)&wt, g_wt);
    cudaGetSymbolAddress((void**)&wo, g_wo);
    cudaGetSymbolAddress((void**)&bc, g_bc);

    const int nx4 = MTOT * EMBED / 4;
    preround<<<(nx4 + 255) / 256, 256>>>(x, xr, 1.0f, nx4);
    transpose_all<<<dim3(EMBED / 32, EMBED / 32, 4), 256>>>(Wq, Wk, Wv, Wo, wt, wo);
    bias_cat<<<(3 * EMBED + 255) / 256, 256>>>(bq, bk, bv, bc);

    cudaFuncSetAttribute(gemm_big, cudaFuncAttributeMaxDynamicSharedMemorySize,
                         GEMM_SMEM);
    cudaFuncSetAttribute(flash_v5, cudaFuncAttributeMaxDynamicSharedMemorySize,
                         FLASH_SMEM);

    // fused QKV: grid (24, 64); Wo: grid (8, 64)
    gemm_big<<<dim3(24, MTOT / 128), 256, GEMM_SMEM>>>(xr, wt, bc, q, k, v, 1);

    flash_v5<<<dim3(BATCH * NHEADS, SEQ / 128), 256, FLASH_SMEM>>>(q, k, v, oa);

    gemm_big<<<dim3(8, MTOT / 128), 256, GEMM_SMEM>>>(oa, wo, bo, out, out, out, 0);
}

// round 11
// speedup vs baseline: 1.5508x; 1.5508x over previous
#include <cuda_runtime.h>
#include <cstdint>

#define EMBED 1024
#define NHEADS 16
#define HDIM 64
#define BATCH 4
#define SEQ 2048
#define MTOT (BATCH * SEQ)   // 8192

// Scratch (static device globals: allowed; no runtime allocation)
__device__ float g_q [(size_t)MTOT * EMBED];
__device__ float g_k [(size_t)MTOT * EMBED];
__device__ float g_v [(size_t)MTOT * EMBED];
__device__ float g_o [(size_t)MTOT * EMBED];
__device__ float g_xr[(size_t)MTOT * EMBED];
__device__ float g_wt[(size_t)3 * EMBED * EMBED];   // [Wq;Wk;Wv] transposed [N][K]
__device__ float g_wo[(size_t)EMBED * EMBED];       // Wo transposed [N][K]
__device__ float g_bc[3 * EMBED];                   // concat bias (q scaled)

__device__ __forceinline__ float rna(float x) {
    float r;
    asm("cvt.rna.tf32.f32 %0, %1;" : "=f"(r) : "f"(x));
    return r;
}
__device__ __forceinline__ uint32_t fbits(float x) { return __float_as_uint(x); }

__device__ __forceinline__ void mma_tf32(float c[4], const uint32_t a[4],
                                         const uint32_t b[2]) {
    asm volatile(
        "mma.sync.aligned.m16n8k8.row.col.f32.tf32.tf32.f32 "
        "{%0,%1,%2,%3}, {%4,%5,%6,%7}, {%8,%9}, {%0,%1,%2,%3};"
        : "+f"(c[0]), "+f"(c[1]), "+f"(c[2]), "+f"(c[3])
        : "r"(a[0]), "r"(a[1]), "r"(a[2]), "r"(a[3]), "r"(b[0]), "r"(b[1]));
}

__device__ __forceinline__ void cp16(void* dst_smem, const void* src) {
    uint32_t d = (uint32_t)__cvta_generic_to_shared(dst_smem);
    asm volatile("cp.async.cg.shared.global [%0], [%1], 16;" :: "r"(d), "l"(src));
}
#define CP_COMMIT() asm volatile("cp.async.commit_group;")
#define CP_WAIT0()  asm volatile("cp.async.wait_group 0;" ::: "memory")

// ---------------------------------------------------------------------------
// elementwise rna (for x)
// ---------------------------------------------------------------------------
__global__ void preround(const float* __restrict__ s, float* __restrict__ d,
                         float sc, int n4)
{
    int i = blockIdx.x * 256 + threadIdx.x;
    if (i < n4) {
        float4 v = ((const float4*)s)[i];
        v.x = rna(v.x * sc); v.y = rna(v.y * sc);
        v.z = rna(v.z * sc); v.w = rna(v.w * sc);
        ((float4*)d)[i] = v;
    }
}

// ---------------------------------------------------------------------------
// all 4 weight transposes in one launch (z picks matrix); Wq folded * 1/8
// ---------------------------------------------------------------------------
__global__ __launch_bounds__(256) void transpose_all(
    const float* __restrict__ Wq, const float* __restrict__ Wk,
    const float* __restrict__ Wv, const float* __restrict__ Wo,
    float* __restrict__ wt, float* __restrict__ wo)
{
    __shared__ float tl[32][33];
    const int z = blockIdx.z;
    const float* src = (z == 0) ? Wq : (z == 1) ? Wk : (z == 2) ? Wv : Wo;
    float* dst = (z == 3) ? wo : wt + (size_t)z * EMBED * EMBED;
    const float sc = (z == 0) ? 0.125f : 1.0f;

    const int tx = threadIdx.x & 31, ty = threadIdx.x >> 5;  // 32 x 8
    const int x0 = blockIdx.x * 32, y0 = blockIdx.y * 32;
    #pragma unroll
    for (int j = 0; j < 32; j += 8)
        tl[ty + j][tx] = rna(src[(size_t)(y0 + ty + j) * EMBED + x0 + tx] * sc);
    __syncthreads();
    #pragma unroll
    for (int j = 0; j < 32; j += 8)
        dst[(size_t)(x0 + ty + j) * EMBED + y0 + tx] = tl[tx][ty + j];
}

// bias concat: bc[0:1024)=bq*0.125, [1024:2048)=bk, [2048:3072)=bv
__global__ void bias_cat(const float* __restrict__ bq, const float* __restrict__ bk,
                         const float* __restrict__ bv, float* __restrict__ bc)
{
    int i = blockIdx.x * 256 + threadIdx.x;
    if (i < EMBED)          bc[i] = bq[i] * 0.125f;
    else if (i < 2 * EMBED) bc[i] = bk[i - EMBED];
    else if (i < 3 * EMBED) bc[i] = bv[i - 2 * EMBED];
}

// ---------------------------------------------------------------------------
// tf32 mma.sync GEMM with k-permuted fragments (frag loads = LDS.64 via
// compiler-schedulable float2 derefs).  Block 128x128, 8 warps (4M x 2N),
// warp tile 32x64, BK=32, 2-stage cp.async, ONE barrier/iter, 2 CTAs/SM.
// smem: As[2][128][40] + Bs[2][128][40] = 81920 B
// ---------------------------------------------------------------------------
#define GPAD 40
#define GEMM_SMEM (2 * 2 * 128 * GPAD * 4)

__global__ __launch_bounds__(256, 2) void gemm_big(
    const float* __restrict__ A, const float* __restrict__ BT,
    const float* __restrict__ bias, float* __restrict__ D0,
    float* __restrict__ D1, float* __restrict__ D2, int round_out)
{
    extern __shared__ float sh[];
    float* As = sh;                      // [2][128][40]
    float* Bs = sh + 2 * 128 * GPAD;     // [2][128][40]

    const int t = threadIdx.x;
    const int lane = t & 31, warp = t >> 5;
    const int g = lane >> 2, e = lane & 3;
    const int m0 = (warp & 3) * 32, n0 = (warp >> 2) * 64;

    const int row0 = blockIdx.y * 128;
    const int bx = blockIdx.x;
    const int id = bx >> 3;                       // which output matrix
    const int col0 = (bx & 7) * 128;              // col within matrix
    float* D = (id == 0) ? D0 : (id == 1) ? D1 : D2;

    // loaders: tiles staged [row][k]; thread covers (row = t>>3 (+32p), k=(t&7)*4)
    const int lr = t >> 3, lk = (t & 7) * 4;
    const float* Ab = A  + (size_t)(row0 + lr) * EMBED + lk;
    const float* Bb = BT + (size_t)(bx * 128 + lr) * EMBED + lk;

    #define GREFILL(k0, buf) do {                                              \
        float* sA = As + (buf) * 128 * GPAD;                                   \
        float* sB = Bs + (buf) * 128 * GPAD;                                   \
        _Pragma("unroll")                                                      \
        for (int p = 0; p < 4; ++p) {                                          \
            cp16(&sA[(lr + 32 * p) * GPAD + lk], Ab + (size_t)(32 * p) * EMBED + (k0)); \
            cp16(&sB[(lr + 32 * p) * GPAD + lk], Bb + (size_t)(32 * p) * EMBED + (k0)); \
        }                                                                      \
        CP_COMMIT();                                                           \
    } while (0)

    GREFILL(0, 0);

    float acc[2][8][4] = {};
    const int NIT = EMBED / 32;

    for (int it = 0; it < NIT; ++it) {
        CP_WAIT0();
        __syncthreads();    // orders: tile landed AND all readers done with buf
        if (it + 1 < NIT) GREFILL((it + 1) * 32, (it + 1) & 1);

        const float* Ac = As + (it & 1) * 128 * GPAD;
        const float* Bc = Bs + (it & 1) * 128 * GPAD;

        #pragma unroll
        for (int ks = 0; ks < 4; ++ks) {
            const int kp = ks * 8 + 2 * e;         // permuted: lanes e -> 2e,2e+1
            uint32_t a[2][4];
            #pragma unroll
            for (int mt = 0; mt < 2; ++mt) {
                const int r = m0 + mt * 16 + g;
                float2 p0 = *(const float2*)&Ac[r * GPAD + kp];
                float2 p1 = *(const float2*)&Ac[(r + 8) * GPAD + kp];
                a[mt][0] = fbits(p0.x); a[mt][2] = fbits(p0.y);
                a[mt][1] = fbits(p1.x); a[mt][3] = fbits(p1.y);
            }
            #pragma unroll
            for (int n = 0; n < 8; ++n) {
                const int br = n0 + n * 8 + g;
                float2 q = *(const float2*)&Bc[br * GPAD + kp];
                uint32_t b[2] = {fbits(q.x), fbits(q.y)};
                mma_tf32(acc[0][n], a[0], b);
                mma_tf32(acc[1][n], a[1], b);
            }
        }
        // no bottom barrier: next iteration's top barrier provides the guard
    }

    // epilogue
    #pragma unroll
    for (int mt = 0; mt < 2; ++mt) {
        const int r = row0 + m0 + mt * 16 + g;
        #pragma unroll
        for (int n = 0; n < 8; ++n) {
            const int cl = col0 + n0 + n * 8 + 2 * e;         // col in matrix
            const int cb = bx * 128 + n0 + n * 8 + 2 * e;     // col in bias buf
            const float b0 = bias[cb], b1 = bias[cb + 1];
            float v00 = acc[mt][n][0] + b0, v01 = acc[mt][n][1] + b1;
            float v10 = acc[mt][n][2] + b0, v11 = acc[mt][n][3] + b1;
            if (round_out) { v00 = rna(v00); v01 = rna(v01);
                             v10 = rna(v10); v11 = rna(v11); }
            *(float2*)&D[(size_t)r * EMBED + cl]       = make_float2(v00, v01);
            *(float2*)&D[(size_t)(r + 8) * EMBED + cl] = make_float2(v10, v11);
        }
    }
}

// ---------------------------------------------------------------------------
// Flash attention v4 (R8-proven): Q-block 128 rows, 8 warps x 16 rows, Bc=64,
// 2-stage cp.async K/V, 2 CTAs/SM.  Q/K permuted k-lanes (LDS.64 frags).
// + alpha==1 rescale skip.
// smem: Ks[2][64][72] Vs[2][64][72] Ps[128][68] = 108544 B
// ---------------------------------------------------------------------------
#define KPAD 72
#define VPAD 72
#define PPAD 68
#define FKS_OFF 0
#define FVS_OFF (2 * 64 * KPAD)
#define FPS_OFF (FVS_OFF + 2 * 64 * VPAD)
#define FLASH_SMEM ((FPS_OFF + 128 * PPAD) * 4)

__global__ __launch_bounds__(256, 2) void flash_v4(
    const float* __restrict__ q, const float* __restrict__ k,
    const float* __restrict__ v, float* __restrict__ o)
{
    extern __shared__ float shf[];
    float* Ks = shf + FKS_OFF;
    float* Vs = shf + FVS_OFF;
    float* Ps = shf + FPS_OFF;

    const int t = threadIdx.x;
    const int lane = t & 31, warp = t >> 5;
    const int g = lane >> 2, e = lane & 3;
    const int m0 = warp * 16;

    const int bh = blockIdx.x;
    const int b = bh >> 4, h = bh & 15;
    const int qrow0 = blockIdx.y * 128;
    const size_t base = ((size_t)b * SEQ) * EMBED + (size_t)h * HDIM;

    const int lkey = t >> 4;          // 0..15
    const int lq4  = (t & 15) * 4;    // 0..60

    // prefetch K/V tile 0 into buf 0
    #pragma unroll
    for (int i = 0; i < 4; ++i) {
        const int key = lkey + 16 * i;
        cp16(&Ks[key * KPAD + lq4], k + base + (size_t)key * EMBED + lq4);
        cp16(&Vs[key * VPAD + lq4], v + base + (size_t)key * EMBED + lq4);
    }
    CP_COMMIT();

    // stage Q (128x64) into Ps, then hoist PERMUTED fragments to registers
    #pragma unroll
    for (int i = 0; i < 8; ++i) {
        const int row = lkey + 16 * i;
        *(float4*)&Ps[row * PPAD + lq4] =
            *(const float4*)(q + base + (size_t)(qrow0 + row) * EMBED + lq4);
    }
    __syncthreads();
    uint32_t qa[8][4];
    #pragma unroll
    for (int ks = 0; ks < 8; ++ks) {
        const int kp = ks * 8 + 2 * e;
        float2 p0 = *(const float2*)&Ps[(m0 + g) * PPAD + kp];
        float2 p1 = *(const float2*)&Ps[(m0 + g + 8) * PPAD + kp];
        qa[ks][0] = fbits(p0.x); qa[ks][2] = fbits(p0.y);
        qa[ks][1] = fbits(p1.x); qa[ks][3] = fbits(p1.y);
    }

    float o_[8][4] = {};
    float mrow[2] = {-1e30f, -1e30f}, lrow[2] = {0.f, 0.f};

    const int NIT = SEQ / 64;
    CP_WAIT0();
    __syncthreads();

    for (int it = 0; it < NIT; ++it) {
        const int bf = it & 1;
        if (it + 1 < NIT) {
            const int nb = bf ^ 1;
            const int kt = (it + 1) * 64;
            #pragma unroll
            for (int i = 0; i < 4; ++i) {
                const int key = lkey + 16 * i;
                cp16(&Ks[nb * 64 * KPAD + key * KPAD + lq4],
                     k + base + (size_t)(kt + key) * EMBED + lq4);
                cp16(&Vs[nb * 64 * VPAD + key * VPAD + lq4],
                     v + base + (size_t)(kt + key) * EMBED + lq4);
            }
            CP_COMMIT();
        }
        const float* Kb = Ks + bf * 64 * KPAD;
        const float* Vb = Vs + bf * 64 * VPAD;

        // S = Q * K^T : permuted k-lanes, K frags via LDS.64
        float s[8][4] = {};
        #pragma unroll
        for (int ks = 0; ks < 8; ++ks) {
            const int kp = ks * 8 + 2 * e;
            #pragma unroll
            for (int n = 0; n < 8; ++n) {
                float2 kk = *(const float2*)&Kb[(n * 8 + g) * KPAD + kp];
                uint32_t bb[2] = {fbits(kk.x), fbits(kk.y)};
                mma_tf32(s[n], qa[ks], bb);
            }
        }

        // online softmax per row-half
        #pragma unroll
        for (int hh = 0; hh < 2; ++hh) {
            const int ci = hh * 2;
            float mx = -1e30f;
            #pragma unroll
            for (int n = 0; n < 8; ++n)
                mx = fmaxf(mx, fmaxf(s[n][ci], s[n][ci + 1]));
            mx = fmaxf(mx, __shfl_xor_sync(0xffffffffu, mx, 1));
            mx = fmaxf(mx, __shfl_xor_sync(0xffffffffu, mx, 2));
            const float mn = fmaxf(mrow[hh], mx);
            const float al = __expf(mrow[hh] - mn);
            mrow[hh] = mn;
            float sum = 0.f;
            #pragma unroll
            for (int n = 0; n < 8; ++n) {
                const float p0 = __expf(s[n][ci] - mn);
                const float p1 = __expf(s[n][ci + 1] - mn);
                s[n][ci] = p0; s[n][ci + 1] = p1;
                sum += p0 + p1;
            }
            sum += __shfl_xor_sync(0xffffffffu, sum, 1);
            sum += __shfl_xor_sync(0xffffffffu, sum, 2);
            lrow[hh] = lrow[hh] * al + sum;
            if (al != 1.0f) {
                #pragma unroll
                for (int n = 0; n < 8; ++n) { o_[n][ci] *= al; o_[n][ci + 1] *= al; }
            }
            const int pr = (m0 + g + 8 * hh) * PPAD;
            #pragma unroll
            for (int n = 0; n < 8; ++n)
                *(float2*)&Ps[pr + n * 8 + 2 * e] =
                    make_float2(rna(s[n][ci]), rna(s[n][ci + 1]));
        }
        __syncwarp();   // Ps rows are per-warp private

        // O += P * V  (standard k-order)
        #pragma unroll
        for (int ks = 0; ks < 8; ++ks) {
            const int k8 = ks * 8;
            uint32_t a[4];
            a[0] = fbits(Ps[(m0 + g) * PPAD + k8 + e]);
            a[1] = fbits(Ps[(m0 + g + 8) * PPAD + k8 + e]);
            a[2] = fbits(Ps[(m0 + g) * PPAD + k8 + e + 4]);
            a[3] = fbits(Ps[(m0 + g + 8) * PPAD + k8 + e + 4]);
            #pragma unroll
            for (int n = 0; n < 8; ++n) {
                uint32_t bb[2];
                bb[0] = fbits(Vb[(k8 + e) * VPAD + n * 8 + g]);
                bb[1] = fbits(Vb[(k8 + e + 4) * VPAD + n * 8 + g]);
                mma_tf32(o_[n], a, bb);
            }
        }

        CP_WAIT0();
        __syncthreads();   // next tile landed; all readers done with bf
    }

    // epilogue: O /= l, rna, write to [B*S, EMBED] at head offset
    #pragma unroll
    for (int hh = 0; hh < 2; ++hh) {
        const float inv = 1.0f / lrow[hh];
        const int row = qrow0 + m0 + g + 8 * hh;
        const int ci = hh * 2;
        #pragma unroll
        for (int n = 0; n < 8; ++n) {
            *(float2*)(o + base + (size_t)row * EMBED + n * 8 + 2 * e) =
                make_float2(rna(o_[n][ci] * inv), rna(o_[n][ci + 1] * inv));
        }
    }
}

// ---------------------------------------------------------------------------
extern "C" void kernel_launch(void* const* d_in, const int* in_sizes, int n_in,
                              void* d_out, int out_size)
{
    const float* x  = (const float*)d_in[0];
    const float* Wq = (const float*)d_in[1];
    const float* bq = (const float*)d_in[2];
    const float* Wk = (const float*)d_in[3];
    const float* bk = (const float*)d_in[4];
    const float* Wv = (const float*)d_in[5];
    const float* bv = (const float*)d_in[6];
    const float* Wo = (const float*)d_in[7];
    const float* bo = (const float*)d_in[8];
    float* out = (float*)d_out;

    float *q, *k, *v, *oa, *xr, *wt, *wo, *bc;
    cudaGetSymbolAddress((void**)&q,  g_q);
    cudaGetSymbolAddress((void**)&k,  g_k);
    cudaGetSymbolAddress((void**)&v,  g_v);
    cudaGetSymbolAddress((void**)&oa, g_o);
    cudaGetSymbolAddress((void**)&xr, g_xr);
    cudaGetSymbolAddress((void**)&wt, g_wt);
    cudaGetSymbolAddress((void**)&wo, g_wo);
    cudaGetSymbolAddress((void**)&bc, g_bc);

    const int nx4 = MTOT * EMBED / 4;
    preround<<<(nx4 + 255) / 256, 256>>>(x, xr, 1.0f, nx4);
    transpose_all<<<dim3(EMBED / 32, EMBED / 32, 4), 256>>>(Wq, Wk, Wv, Wo, wt, wo);
    bias_cat<<<(3 * EMBED + 255) / 256, 256>>>(bq, bk, bv, bc);

    cudaFuncSetAttribute(gemm_big, cudaFuncAttributeMaxDynamicSharedMemorySize,
                         GEMM_SMEM);
    cudaFuncSetAttribute(flash_v4, cudaFuncAttributeMaxDynamicSharedMemorySize,
                         FLASH_SMEM);

    // fused QKV: grid (24, 64); Wo: grid (8, 64)
    gemm_big<<<dim3(24, MTOT / 128), 256, GEMM_SMEM>>>(xr, wt, bc, q, k, v, 1);

    flash_v4<<<dim3(BATCH * NHEADS, SEQ / 128), 256, FLASH_SMEM>>>(q, k, v, oa);

    gemm_big<<<dim3(8, MTOT / 128), 256, GEMM_SMEM>>>(oa, wo, bo, out, out, out, 0);
}

// round 13
// speedup vs baseline: 2.5129x; 1.6204x over previous
#include <cuda_runtime.h>
#include <cuda_fp16.h>
#include <cstdint>

#define EMBED 1024
#define NHEADS 16
#define HDIM 64
#define BATCH 4
#define SEQ 2048
#define MTOT (BATCH * SEQ)   // 8192

// Scratch (static device globals: allowed; no runtime allocation)
__device__ __half g_xh [(size_t)MTOT * EMBED];
__device__ __half g_qh [(size_t)MTOT * EMBED];
__device__ __half g_kh [(size_t)MTOT * EMBED];
__device__ __half g_vh [(size_t)MTOT * EMBED];
__device__ __half g_oh [(size_t)MTOT * EMBED];
__device__ __half g_wth[(size_t)3 * EMBED * EMBED];  // [Wq;Wk;Wv]^T  [N][K]
__device__ __half g_woh[(size_t)EMBED * EMBED];      // Wo^T          [N][K]
__device__ float  g_bc [3 * EMBED];                  // concat bias (q scaled)

__device__ __forceinline__ uint32_t fbits(float x) { return __float_as_uint(x); }

// D(16x8,f32) += A(16x16,f16) * B(16x8,f16)
__device__ __forceinline__ void mma_f16(float c[4], const uint32_t a[4],
                                        uint32_t b0, uint32_t b1) {
    asm volatile(
        "mma.sync.aligned.m16n8k16.row.col.f32.f16.f16.f32 "
        "{%0,%1,%2,%3}, {%4,%5,%6,%7}, {%8,%9}, {%0,%1,%2,%3};"
        : "+f"(c[0]), "+f"(c[1]), "+f"(c[2]), "+f"(c[3])
        : "r"(a[0]), "r"(a[1]), "r"(a[2]), "r"(a[3]), "r"(b0), "r"(b1));
}

// transposed 8x8 b16 tile pair (b-frags from row-major [k][n] smem)
__device__ __forceinline__ void ldsm_x2_t(uint32_t& r0, uint32_t& r1, uint32_t a) {
    asm volatile("ldmatrix.sync.aligned.m8n8.x2.trans.shared.b16 {%0,%1}, [%2];"
                 : "=r"(r0), "=r"(r1) : "r"(a));
}

__device__ __forceinline__ void cp16(void* dst_smem, const void* src) {
    uint32_t d = (uint32_t)__cvta_generic_to_shared(dst_smem);
    asm volatile("cp.async.cg.shared.global [%0], [%1], 16;" :: "r"(d), "l"(src));
}
#define CP_COMMIT() asm volatile("cp.async.commit_group;")
#define CP_WAIT0()  asm volatile("cp.async.wait_group 0;" ::: "memory")

__device__ __forceinline__ uint32_t smem_u32(const void* p) {
    return (uint32_t)__cvta_generic_to_shared(p);
}

// ---------------------------------------------------------------------------
// fp32 -> fp16 elementwise (for x)
// ---------------------------------------------------------------------------
__global__ void tohalf(const float* __restrict__ s, __half* __restrict__ d, int n4)
{
    int i = blockIdx.x * 256 + threadIdx.x;
    if (i < n4) {
        float4 v = ((const float4*)s)[i];
        ((__half2*)d)[2 * i]     = __floats2half2_rn(v.x, v.y);
        ((__half2*)d)[2 * i + 1] = __floats2half2_rn(v.z, v.w);
    }
}

// ---------------------------------------------------------------------------
// all 4 weight transposes -> fp16 in one launch (z picks matrix); Wq * 1/8
// ---------------------------------------------------------------------------
__global__ __launch_bounds__(256) void transpose_half(
    const float* __restrict__ Wq, const float* __restrict__ Wk,
    const float* __restrict__ Wv, const float* __restrict__ Wo,
    __half* __restrict__ wt, __half* __restrict__ wo)
{
    __shared__ float tl[32][33];
    const int z = blockIdx.z;
    const float* src = (z == 0) ? Wq : (z == 1) ? Wk : (z == 2) ? Wv : Wo;
    __half* dst = (z == 3) ? wo : wt + (size_t)z * EMBED * EMBED;
    const float sc = (z == 0) ? 0.125f : 1.0f;

    const int tx = threadIdx.x & 31, ty = threadIdx.x >> 5;  // 32 x 8
    const int x0 = blockIdx.x * 32, y0 = blockIdx.y * 32;
    #pragma unroll
    for (int j = 0; j < 32; j += 8)
        tl[ty + j][tx] = src[(size_t)(y0 + ty + j) * EMBED + x0 + tx] * sc;
    __syncthreads();
    #pragma unroll
    for (int j = 0; j < 32; j += 8)
        dst[(size_t)(x0 + ty + j) * EMBED + y0 + tx] = __float2half_rn(tl[tx][ty + j]);
}

// bias concat: bc[0:1024)=bq*0.125, [1024:2048)=bk, [2048:3072)=bv
__global__ void bias_cat(const float* __restrict__ bq, const float* __restrict__ bk,
                         const float* __restrict__ bv, float* __restrict__ bc)
{
    int i = blockIdx.x * 256 + threadIdx.x;
    if (i < EMBED)          bc[i] = bq[i] * 0.125f;
    else if (i < 2 * EMBED) bc[i] = bk[i - EMBED];
    else if (i < 3 * EMBED) bc[i] = bv[i - 2 * EMBED];
}

// ---------------------------------------------------------------------------
// fp16 mma.sync GEMM (m16n8k16): block 128x128, 8 warps (4M x 2N),
// warp tile 32x64, BK=32 halves (2 k16 steps), 2-stage cp.async, 2 CTAs/SM.
// Tiles [row][k] halves, row stride 40 (20 words: 20g+e injective mod 32).
// fp32out=0: route fp16 output to Q/K/V by n-block;  fp32out=1: final fp32.
// smem: 2 x (A 128x40 + B 128x40) halves = 40960 B
// ---------------------------------------------------------------------------
#define GPADH 40
#define GEMM_SMEM (2 * 2 * 128 * GPADH * 2)

__global__ __launch_bounds__(256, 2) void gemm_h(
    const __half* __restrict__ A, const __half* __restrict__ BT,
    const float* __restrict__ bias, void* P0, void* P1, void* P2, int fp32out)
{
    extern __shared__ __half shh[];
    __half* As = shh;                       // [2][128][40]
    __half* Bs = shh + 2 * 128 * GPADH;     // [2][128][40]

    const int t = threadIdx.x;
    const int lane = t & 31, warp = t >> 5;
    const int g = lane >> 2, e = lane & 3;
    const int m0 = (warp & 3) * 32, n0 = (warp >> 2) * 64;

    const int row0 = blockIdx.y * 128;
    const int bx = blockIdx.x;
    const int id = bx >> 3;                       // output matrix (qkv mode)
    const int col0 = (bx & 7) * 128;              // col within matrix

    // loaders: thread covers (row = t>>2 (+64p), 16B chunk = t&3)
    const int lr = t >> 2, lc = (t & 3) * 8;      // lc in halves
    const __half* Ab = A  + (size_t)(row0 + lr) * EMBED + lc;
    const __half* Bb = BT + (size_t)(bx * 128 + lr) * EMBED + lc;

    #define GREFILL(k0, buf) do {                                              \
        __half* sA = As + (buf) * 128 * GPADH;                                 \
        __half* sB = Bs + (buf) * 128 * GPADH;                                 \
        _Pragma("unroll")                                                      \
        for (int p = 0; p < 2; ++p) {                                          \
            cp16(&sA[(lr + 64 * p) * GPADH + lc], Ab + (size_t)(64 * p) * EMBED + (k0)); \
            cp16(&sB[(lr + 64 * p) * GPADH + lc], Bb + (size_t)(64 * p) * EMBED + (k0)); \
        }                                                                      \
        CP_COMMIT();                                                           \
    } while (0)

    GREFILL(0, 0);

    float acc[2][8][4] = {};
    const int NIT = EMBED / 32;

    for (int it = 0; it < NIT; ++it) {
        CP_WAIT0();
        __syncthreads();
        if (it + 1 < NIT) GREFILL((it + 1) * 32, (it + 1) & 1);

        const __half* Ac = As + (it & 1) * 128 * GPADH;
        const __half* Bc = Bs + (it & 1) * 128 * GPADH;

        #pragma unroll
        for (int ks = 0; ks < 2; ++ks) {
            const int kh = ks * 16 + 2 * e;       // half offset of a0/b0
            uint32_t a[2][4];
            #pragma unroll
            for (int mt = 0; mt < 2; ++mt) {
                const int r = m0 + mt * 16 + g;
                a[mt][0] = *(const uint32_t*)&Ac[r * GPADH + kh];
                a[mt][1] = *(const uint32_t*)&Ac[(r + 8) * GPADH + kh];
                a[mt][2] = *(const uint32_t*)&Ac[r * GPADH + kh + 8];
                a[mt][3] = *(const uint32_t*)&Ac[(r + 8) * GPADH + kh + 8];
            }
            #pragma unroll
            for (int n = 0; n < 8; ++n) {
                const int br = n0 + n * 8 + g;
                uint32_t b0 = *(const uint32_t*)&Bc[br * GPADH + kh];
                uint32_t b1 = *(const uint32_t*)&Bc[br * GPADH + kh + 8];
                mma_f16(acc[0][n], a[0], b0, b1);
                mma_f16(acc[1][n], a[1], b0, b1);
            }
        }
    }

    // epilogue
    #pragma unroll
    for (int mt = 0; mt < 2; ++mt) {
        const int r = row0 + m0 + mt * 16 + g;
        #pragma unroll
        for (int n = 0; n < 8; ++n) {
            const int cl = col0 + n0 + n * 8 + 2 * e;         // col in matrix
            const int cb = bx * 128 + n0 + n * 8 + 2 * e;     // col in bias buf
            const float b0 = bias[cb], b1 = bias[cb + 1];
            const float v00 = acc[mt][n][0] + b0, v01 = acc[mt][n][1] + b1;
            const float v10 = acc[mt][n][2] + b0, v11 = acc[mt][n][3] + b1;
            if (fp32out) {
                float* D = (float*)P0;
                *(float2*)&D[(size_t)r * EMBED + cl]       = make_float2(v00, v01);
                *(float2*)&D[(size_t)(r + 8) * EMBED + cl] = make_float2(v10, v11);
            } else {
                __half* D = (__half*)((id == 0) ? P0 : (id == 1) ? P1 : P2);
                *(__half2*)&D[(size_t)r * EMBED + cl]       = __floats2half2_rn(v00, v01);
                *(__half2*)&D[(size_t)(r + 8) * EMBED + cl] = __floats2half2_rn(v10, v11);
            }
        }
    }
}

// ---------------------------------------------------------------------------
// Flash attention fp16 (m16n8k16): Q-block 128 rows, 8 warps x 16 rows,
// Bc=64, 2-stage cp.async K/V, 2 CTAs/SM.  Q frags hoisted; S-mma B = plain
// word loads from K; PV B via ldmatrix.x2.trans on naturally-staged V.
// smem (halves): Ks[2][64][72] Vs[2][64][72] Ps[128][72] = 55296 B
// ---------------------------------------------------------------------------
#define FROW 72                         // halves per smem row (36 words: 4g+e ok)
#define FKS_OFF 0
#define FVS_OFF (2 * 64 * FROW)
#define FPS_OFF (FVS_OFF + 2 * 64 * FROW)
#define FLASH_SMEM ((FPS_OFF + 128 * FROW) * 2)

__global__ __launch_bounds__(256, 2) void flash_h(
    const __half* __restrict__ q, const __half* __restrict__ k,
    const __half* __restrict__ v, __half* __restrict__ o)
{
    extern __shared__ __half shf[];
    __half* Ks = shf + FKS_OFF;
    __half* Vs = shf + FVS_OFF;
    __half* Ps = shf + FPS_OFF;

    const int t = threadIdx.x;
    const int lane = t & 31, warp = t >> 5;
    const int g = lane >> 2, e = lane & 3;
    const int m0 = warp * 16;

    const int bh = blockIdx.x;
    const int b = bh >> 4, h = bh & 15;
    const int qrow0 = blockIdx.y * 128;
    const size_t base = ((size_t)b * SEQ) * EMBED + (size_t)h * HDIM;

    // K/V loaders: idx = t + 256p -> (row = idx>>3, chunk = idx&7), 16B chunks
    // prefetch K/V tile 0 into buf 0
    #pragma unroll
    for (int p = 0; p < 2; ++p) {
        const int idx = t + 256 * p;
        const int row = idx >> 3, ch = (idx & 7) * 8;
        cp16(&Ks[row * FROW + ch], k + base + (size_t)row * EMBED + ch);
        cp16(&Vs[row * FROW + ch], v + base + (size_t)row * EMBED + ch);
    }
    CP_COMMIT();

    // stage Q (128 x 64 halves) into Ps, hoist fragments
    #pragma unroll
    for (int i = 0; i < 4; ++i) {
        const int idx = t + 256 * i;
        const int row = idx >> 3, ch = (idx & 7) * 8;
        *(uint4*)&Ps[row * FROW + ch] =
            *(const uint4*)(q + base + (size_t)(qrow0 + row) * EMBED + ch);
    }
    __syncthreads();
    uint32_t qa[4][4];
    #pragma unroll
    for (int c = 0; c < 4; ++c) {
        const int kh = c * 16 + 2 * e;
        qa[c][0] = *(const uint32_t*)&Ps[(m0 + g) * FROW + kh];
        qa[c][1] = *(const uint32_t*)&Ps[(m0 + g + 8) * FROW + kh];
        qa[c][2] = *(const uint32_t*)&Ps[(m0 + g) * FROW + kh + 8];
        qa[c][3] = *(const uint32_t*)&Ps[(m0 + g + 8) * FROW + kh + 8];
    }

    // ldmatrix lane base for V (lanes 0-15 supply 16 key-row pointers)
    const uint32_t vLane = smem_u32(Vs) + (uint32_t)((lane & 15) * FROW) * 2;

    float o_[8][4] = {};
    float mrow[2] = {-1e30f, -1e30f}, lrow[2] = {0.f, 0.f};

    const int NIT = SEQ / 64;
    CP_WAIT0();
    __syncthreads();

    for (int it = 0; it < NIT; ++it) {
        const int bf = it & 1;
        if (it + 1 < NIT) {
            const int nb = bf ^ 1;
            const int kt = (it + 1) * 64;
            #pragma unroll
            for (int p = 0; p < 2; ++p) {
                const int idx = t + 256 * p;
                const int row = idx >> 3, ch = (idx & 7) * 8;
                cp16(&Ks[nb * 64 * FROW + row * FROW + ch],
                     k + base + (size_t)(kt + row) * EMBED + ch);
                cp16(&Vs[nb * 64 * FROW + row * FROW + ch],
                     v + base + (size_t)(kt + row) * EMBED + ch);
            }
            CP_COMMIT();
        }
        const __half* Kb = Ks + bf * 64 * FROW;

        // S = Q * K^T : 32 mmas (4 k16-chunks x 8 n-tiles)
        float s[8][4] = {};
        #pragma unroll
        for (int c = 0; c < 4; ++c) {
            const int kh = c * 16 + 2 * e;
            #pragma unroll
            for (int n = 0; n < 8; ++n) {
                uint32_t b0 = *(const uint32_t*)&Kb[(n * 8 + g) * FROW + kh];
                uint32_t b1 = *(const uint32_t*)&Kb[(n * 8 + g) * FROW + kh + 8];
                mma_f16(s[n], qa[c], b0, b1);
            }
        }

        // online softmax per row-half (fp32)
        #pragma unroll
        for (int hh = 0; hh < 2; ++hh) {
            const int ci = hh * 2;
            float mx = -1e30f;
            #pragma unroll
            for (int n = 0; n < 8; ++n)
                mx = fmaxf(mx, fmaxf(s[n][ci], s[n][ci + 1]));
            mx = fmaxf(mx, __shfl_xor_sync(0xffffffffu, mx, 1));
            mx = fmaxf(mx, __shfl_xor_sync(0xffffffffu, mx, 2));
            const float mn = fmaxf(mrow[hh], mx);
            const float al = __expf(mrow[hh] - mn);
            mrow[hh] = mn;
            float sum = 0.f;
            #pragma unroll
            for (int n = 0; n < 8; ++n) {
                const float p0 = __expf(s[n][ci] - mn);
                const float p1 = __expf(s[n][ci + 1] - mn);
                s[n][ci] = p0; s[n][ci + 1] = p1;
                sum += p0 + p1;
            }
            sum += __shfl_xor_sync(0xffffffffu, sum, 1);
            sum += __shfl_xor_sync(0xffffffffu, sum, 2);
            lrow[hh] = lrow[hh] * al + sum;
            if (al != 1.0f) {
                #pragma unroll
                for (int n = 0; n < 8; ++n) { o_[n][ci] *= al; o_[n][ci + 1] *= al; }
            }
            const int pr = (m0 + g + 8 * hh) * FROW;
            #pragma unroll
            for (int n = 0; n < 8; ++n)
                *(__half2*)&Ps[pr + n * 8 + 2 * e] =
                    __floats2half2_rn(s[n][ci], s[n][ci + 1]);
        }
        __syncwarp();   // Ps rows are per-warp private

        // O += P * V : P plain word loads, V via ldmatrix.trans (one ahead)
        const uint32_t vBase = vLane + (uint32_t)(bf * 64 * FROW) * 2;
        #pragma unroll
        for (int ks = 0; ks < 4; ++ks) {
            const int kh = ks * 16 + 2 * e;
            uint32_t a[4];
            a[0] = *(const uint32_t*)&Ps[(m0 + g) * FROW + kh];
            a[1] = *(const uint32_t*)&Ps[(m0 + g + 8) * FROW + kh];
            a[2] = *(const uint32_t*)&Ps[(m0 + g) * FROW + kh + 8];
            a[3] = *(const uint32_t*)&Ps[(m0 + g + 8) * FROW + kh + 8];
            const uint32_t vRow = vBase + (uint32_t)(ks * 16 * FROW) * 2;
            uint32_t vb0[2], vb1[2];
            ldsm_x2_t(vb0[0], vb1[0], vRow);
            #pragma unroll
            for (int n = 0; n < 8; ++n) {
                if (n < 7) ldsm_x2_t(vb0[(n + 1) & 1], vb1[(n + 1) & 1],
                                     vRow + (n + 1) * 16);
                mma_f16(o_[n], a, vb0[n & 1], vb1[n & 1]);
            }
        }

        CP_WAIT0();
        __syncthreads();   // next tile landed; all readers done with bf
    }

    // epilogue: O /= l, convert fp16, write [B*S, EMBED] at head offset
    #pragma unroll
    for (int hh = 0; hh < 2; ++hh) {
        const float inv = 1.0f / lrow[hh];
        const int row = qrow0 + m0 + g + 8 * hh;
        const int ci = hh * 2;
        #pragma unroll
        for (int n = 0; n < 8; ++n) {
            *(__half2*)(o + base + (size_t)row * EMBED + n * 8 + 2 * e) =
                __floats2half2_rn(o_[n][ci] * inv, o_[n][ci + 1] * inv);
        }
    }
}

// ---------------------------------------------------------------------------
extern "C" void kernel_launch(void* const* d_in, const int* in_sizes, int n_in,
                              void* d_out, int out_size)
{
    const float* x  = (const float*)d_in[0];
    const float* Wq = (const float*)d_in[1];
    const float* bq = (const float*)d_in[2];
    const float* Wk = (const float*)d_in[3];
    const float* bk = (const float*)d_in[4];
    const float* Wv = (const float*)d_in[5];
    const float* bv = (const float*)d_in[6];
    const float* Wo = (const float*)d_in[7];
    const float* bo = (const float*)d_in[8];
    float* out = (float*)d_out;

    __half *xh, *qh, *kh, *vh, *oh, *wth, *woh;
    float *bc;
    cudaGetSymbolAddress((void**)&xh,  g_xh);
    cudaGetSymbolAddress((void**)&qh,  g_qh);
    cudaGetSymbolAddress((void**)&kh,  g_kh);
    cudaGetSymbolAddress((void**)&vh,  g_vh);
    cudaGetSymbolAddress((void**)&oh,  g_oh);
    cudaGetSymbolAddress((void**)&wth, g_wth);
    cudaGetSymbolAddress((void**)&woh, g_woh);
    cudaGetSymbolAddress((void**)&bc,  g_bc);

    const int nx4 = MTOT * EMBED / 4;
    tohalf<<<(nx4 + 255) / 256, 256>>>(x, xh, nx4);
    transpose_half<<<dim3(EMBED / 32, EMBED / 32, 4), 256>>>(Wq, Wk, Wv, Wo, wth, woh);
    bias_cat<<<(3 * EMBED + 255) / 256, 256>>>(bq, bk, bv, bc);

    cudaFuncSetAttribute(gemm_h, cudaFuncAttributeMaxDynamicSharedMemorySize,
                         GEMM_SMEM);
    cudaFuncSetAttribute(flash_h, cudaFuncAttributeMaxDynamicSharedMemorySize,
                         FLASH_SMEM);

    // fused QKV: grid (24, 64) -> fp16 q/k/v
    gemm_h<<<dim3(24, MTOT / 128), 256, GEMM_SMEM>>>(xh, wth, bc, qh, kh, vh, 0);

    flash_h<<<dim3(BATCH * NHEADS, SEQ / 128), 256, FLASH_SMEM>>>(qh, kh, vh, oh);

    // output projection: grid (8, 64) -> fp32 out
    gemm_h<<<dim3(8, MTOT / 128), 256, GEMM_SMEM>>>(oh, woh, bo, out, out, out, 1);
}

// round 16
// speedup vs baseline: 2.7322x; 1.0873x over previous
#include <cuda_runtime.h>
#include <cuda_fp16.h>
#include <cstdint>

#define EMBED 1024
#define NHEADS 16
#define HDIM 64
#define BATCH 4
#define SEQ 2048
#define MTOT (BATCH * SEQ)   // 8192

// q pre-scale: (1/sqrt(64)) * log2(e)  -> softmax computed base-2
#define QSCALE 0.18033688011112042f

// Scratch (static device globals: allowed; no runtime allocation)
__device__ __half g_xh [(size_t)MTOT * EMBED];
__device__ __half g_qh [(size_t)MTOT * EMBED];
__device__ __half g_kh [(size_t)MTOT * EMBED];
__device__ __half g_vh [(size_t)MTOT * EMBED];
__device__ __half g_oh [(size_t)MTOT * EMBED];
__device__ __half g_wth[(size_t)3 * EMBED * EMBED];  // [Wq;Wk;Wv]^T  [N][K]
__device__ __half g_woh[(size_t)EMBED * EMBED];      // Wo^T          [N][K]
__device__ float  g_bc [3 * EMBED];                  // concat bias (q scaled)

// D(16x8,f32) += A(16x16,f16) * B(16x8,f16)
__device__ __forceinline__ void mma_f16(float c[4], const uint32_t a[4],
                                        uint32_t b0, uint32_t b1) {
    asm volatile(
        "mma.sync.aligned.m16n8k16.row.col.f32.f16.f16.f32 "
        "{%0,%1,%2,%3}, {%4,%5,%6,%7}, {%8,%9}, {%0,%1,%2,%3};"
        : "+f"(c[0]), "+f"(c[1]), "+f"(c[2]), "+f"(c[3])
        : "r"(a[0]), "r"(a[1]), "r"(a[2]), "r"(a[3]), "r"(b0), "r"(b1));
}

// transposed 8x8 b16 tile pair (b-frags from row-major [k][n] smem)
__device__ __forceinline__ void ldsm_x2_t(uint32_t& r0, uint32_t& r1, uint32_t a) {
    asm volatile("ldmatrix.sync.aligned.m8n8.x2.trans.shared.b16 {%0,%1}, [%2];"
                 : "=r"(r0), "=r"(r1) : "r"(a));
}

__device__ __forceinline__ void cp16(void* dst_smem, const void* src) {
    uint32_t d = (uint32_t)__cvta_generic_to_shared(dst_smem);
    asm volatile("cp.async.cg.shared.global [%0], [%1], 16;" :: "r"(d), "l"(src));
}
#define CP_COMMIT() asm volatile("cp.async.commit_group;")
#define CP_WAIT0()  asm volatile("cp.async.wait_group 0;" ::: "memory")

__device__ __forceinline__ uint32_t smem_u32(const void* p) {
    return (uint32_t)__cvta_generic_to_shared(p);
}
__device__ __forceinline__ float ex2(float x) {
    float r;
    asm("ex2.approx.f32 %0, %1;" : "=f"(r) : "f"(x));
    return r;
}

// ---------------------------------------------------------------------------
// fp32 -> fp16 elementwise (for x)
// ---------------------------------------------------------------------------
__global__ void tohalf(const float* __restrict__ s, __half* __restrict__ d, int n4)
{
    int i = blockIdx.x * 256 + threadIdx.x;
    if (i < n4) {
        float4 v = ((const float4*)s)[i];
        ((__half2*)d)[2 * i]     = __floats2half2_rn(v.x, v.y);
        ((__half2*)d)[2 * i + 1] = __floats2half2_rn(v.z, v.w);
    }
}

// ---------------------------------------------------------------------------
// all 4 weight transposes -> fp16 in one launch (z picks matrix); Wq * QSCALE
// ---------------------------------------------------------------------------
__global__ __launch_bounds__(256) void transpose_half(
    const float* __restrict__ Wq, const float* __restrict__ Wk,
    const float* __restrict__ Wv, const float* __restrict__ Wo,
    __half* __restrict__ wt, __half* __restrict__ wo)
{
    __shared__ float tl[32][33];
    const int z = blockIdx.z;
    const float* src = (z == 0) ? Wq : (z == 1) ? Wk : (z == 2) ? Wv : Wo;
    __half* dst = (z == 3) ? wo : wt + (size_t)z * EMBED * EMBED;
    const float sc = (z == 0) ? QSCALE : 1.0f;

    const int tx = threadIdx.x & 31, ty = threadIdx.x >> 5;  // 32 x 8
    const int x0 = blockIdx.x * 32, y0 = blockIdx.y * 32;
    #pragma unroll
    for (int j = 0; j < 32; j += 8)
        tl[ty + j][tx] = src[(size_t)(y0 + ty + j) * EMBED + x0 + tx] * sc;
    __syncthreads();
    #pragma unroll
    for (int j = 0; j < 32; j += 8)
        dst[(size_t)(x0 + ty + j) * EMBED + y0 + tx] = __float2half_rn(tl[tx][ty + j]);
}

// bias concat: bc[0:1024)=bq*QSCALE, [1024:2048)=bk, [2048:3072)=bv
__global__ void bias_cat(const float* __restrict__ bq, const float* __restrict__ bk,
                         const float* __restrict__ bv, float* __restrict__ bc)
{
    int i = blockIdx.x * 256 + threadIdx.x;
    if (i < EMBED)          bc[i] = bq[i] * QSCALE;
    else if (i < 2 * EMBED) bc[i] = bk[i - EMBED];
    else if (i < 3 * EMBED) bc[i] = bv[i - 2 * EMBED];
}

// ---------------------------------------------------------------------------
// fp16 mma.sync GEMM (m16n8k16): block 128x128, 8 warps (4M x 2N),
// warp tile 32x64, BK=64 halves (4 k16 steps), 2-stage cp.async, 2 CTAs/SM.
// Tiles [row][k] halves, row stride 72 (36 words: banks 4g+8ks+e, all
// distinct mod 32 -> conflict-free).
// fp32out=0: route fp16 output to Q/K/V by n-block;  fp32out=1: final fp32.
// smem: 2 x (A 128x72 + B 128x72) halves = 73728 B
// ---------------------------------------------------------------------------
#define GPADH 72
#define GEMM_SMEM (2 * 2 * 128 * GPADH * 2)

__global__ __launch_bounds__(256, 2) void gemm_h(
    const __half* __restrict__ A, const __half* __restrict__ BT,
    const float* __restrict__ bias, void* P0, void* P1, void* P2, int fp32out)
{
    extern __shared__ __half shh[];
    __half* As = shh;                       // [2][128][72]
    __half* Bs = shh + 2 * 128 * GPADH;     // [2][128][72]

    const int t = threadIdx.x;
    const int lane = t & 31, warp = t >> 5;
    const int g = lane >> 2, e = lane & 3;
    const int m0 = (warp & 3) * 32, n0 = (warp >> 2) * 64;

    const int row0 = blockIdx.y * 128;
    const int bx = blockIdx.x;
    const int id = bx >> 3;                       // output matrix (qkv mode)
    const int col0 = (bx & 7) * 128;              // col within matrix

    // loaders: thread covers (row = t>>3 (+32p), 16B chunk = t&7)
    const int lr = t >> 3, lc = (t & 7) * 8;      // lc in halves
    const __half* Ab = A  + (size_t)(row0 + lr) * EMBED + lc;
    const __half* Bb = BT + (size_t)(bx * 128 + lr) * EMBED + lc;

    #define GREFILL(k0, buf) do {                                              \
        __half* sA = As + (buf) * 128 * GPADH;                                 \
        __half* sB = Bs + (buf) * 128 * GPADH;                                 \
        _Pragma("unroll")                                                      \
        for (int p = 0; p < 4; ++p) {                                          \
            cp16(&sA[(lr + 32 * p) * GPADH + lc], Ab + (size_t)(32 * p) * EMBED + (k0)); \
            cp16(&sB[(lr + 32 * p) * GPADH + lc], Bb + (size_t)(32 * p) * EMBED + (k0)); \
        }                                                                      \
        CP_COMMIT();                                                           \
    } while (0)

    GREFILL(0, 0);

    float acc[2][8][4] = {};
    const int NIT = EMBED / 64;     // 16

    for (int it = 0; it < NIT; ++it) {
        CP_WAIT0();
        __syncthreads();
        if (it + 1 < NIT) GREFILL((it + 1) * 64, (it + 1) & 1);

        const __half* Ac = As + (it & 1) * 128 * GPADH;
        const __half* Bc = Bs + (it & 1) * 128 * GPADH;

        #pragma unroll
        for (int ks = 0; ks < 4; ++ks) {
            const int kh = ks * 16 + 2 * e;       // half offset of a0/b0
            uint32_t a[2][4];
            #pragma unroll
            for (int mt = 0; mt < 2; ++mt) {
                const int r = m0 + mt * 16 + g;
                a[mt][0] = *(const uint32_t*)&Ac[r * GPADH + kh];
                a[mt][1] = *(const uint32_t*)&Ac[(r + 8) * GPADH + kh];
                a[mt][2] = *(const uint32_t*)&Ac[r * GPADH + kh + 8];
                a[mt][3] = *(const uint32_t*)&Ac[(r + 8) * GPADH + kh + 8];
            }
            #pragma unroll
            for (int n = 0; n < 8; ++n) {
                const int br = n0 + n * 8 + g;
                uint32_t b0 = *(const uint32_t*)&Bc[br * GPADH + kh];
                uint32_t b1 = *(const uint32_t*)&Bc[br * GPADH + kh + 8];
                mma_f16(acc[0][n], a[0], b0, b1);
                mma_f16(acc[1][n], a[1], b0, b1);
            }
        }
    }

    // epilogue
    #pragma unroll
    for (int mt = 0; mt < 2; ++mt) {
        const int r = row0 + m0 + mt * 16 + g;
        #pragma unroll
        for (int n = 0; n < 8; ++n) {
            const int cl = col0 + n0 + n * 8 + 2 * e;         // col in matrix
            const int cb = bx * 128 + n0 + n * 8 + 2 * e;     // col in bias buf
            const float b0 = bias[cb], b1 = bias[cb + 1];
            const float v00 = acc[mt][n][0] + b0, v01 = acc[mt][n][1] + b1;
            const float v10 = acc[mt][n][2] + b0, v11 = acc[mt][n][3] + b1;
            if (fp32out) {
                float* D = (float*)P0;
                *(float2*)&D[(size_t)r * EMBED + cl]       = make_float2(v00, v01);
                *(float2*)&D[(size_t)(r + 8) * EMBED + cl] = make_float2(v10, v11);
            } else {
                __half* D = (__half*)((id == 0) ? P0 : (id == 1) ? P1 : P2);
                *(__half2*)&D[(size_t)r * EMBED + cl]       = __floats2half2_rn(v00, v01);
                *(__half2*)&D[(size_t)(r + 8) * EMBED + cl] = __floats2half2_rn(v10, v11);
            }
        }
    }
}

// ---------------------------------------------------------------------------
// Flash attention fp16 (m16n8k16): Q-block 128 rows, 8 warps x 16 rows,
// Bc=64, 2-stage cp.async K/V, 2 CTAs/SM.  Softmax in base-2 (log2e folded
// into q): ex2.approx only, no FMUL.  PV B via ldmatrix.x2.trans.
// smem (halves): Ks[2][64][72] Vs[2][64][72] Ps[128][72] = 55296 B
// ---------------------------------------------------------------------------
#define FROW 72                         // halves per smem row (36 words: 4g+e ok)
#define FKS_OFF 0
#define FVS_OFF (2 * 64 * FROW)
#define FPS_OFF (FVS_OFF + 2 * 64 * FROW)
#define FLASH_SMEM ((FPS_OFF + 128 * FROW) * 2)

__global__ __launch_bounds__(256, 2) void flash_h(
    const __half* __restrict__ q, const __half* __restrict__ k,
    const __half* __restrict__ v, __half* __restrict__ o)
{
    extern __shared__ __half shf[];
    __half* Ks = shf + FKS_OFF;
    __half* Vs = shf + FVS_OFF;
    __half* Ps = shf + FPS_OFF;

    const int t = threadIdx.x;
    const int lane = t & 31, warp = t >> 5;
    const int g = lane >> 2, e = lane & 3;
    const int m0 = warp * 16;

    const int bh = blockIdx.x;
    const int b = bh >> 4, h = bh & 15;
    const int qrow0 = blockIdx.y * 128;
    const size_t base = ((size_t)b * SEQ) * EMBED + (size_t)h * HDIM;

    // prefetch K/V tile 0 into buf 0 (idx -> row = idx>>3, 16B chunk = idx&7)
    #pragma unroll
    for (int p = 0; p < 2; ++p) {
        const int idx = t + 256 * p;
        const int row = idx >> 3, ch = (idx & 7) * 8;
        cp16(&Ks[row * FROW + ch], k + base + (size_t)row * EMBED + ch);
        cp16(&Vs[row * FROW + ch], v + base + (size_t)row * EMBED + ch);
    }
    CP_COMMIT();

    // stage Q (128 x 64 halves) into Ps, hoist fragments
    #pragma unroll
    for (int i = 0; i < 4; ++i) {
        const int idx = t + 256 * i;
        const int row = idx >> 3, ch = (idx & 7) * 8;
        *(uint4*)&Ps[row * FROW + ch] =
            *(const uint4*)(q + base + (size_t)(qrow0 + row) * EMBED + ch);
    }
    __syncthreads();
    uint32_t qa[4][4];
    #pragma unroll
    for (int c = 0; c < 4; ++c) {
        const int kh = c * 16 + 2 * e;
        qa[c][0] = *(const uint32_t*)&Ps[(m0 + g) * FROW + kh];
        qa[c][1] = *(const uint32_t*)&Ps[(m0 + g + 8) * FROW + kh];
        qa[c][2] = *(const uint32_t*)&Ps[(m0 + g) * FROW + kh + 8];
        qa[c][3] = *(const uint32_t*)&Ps[(m0 + g + 8) * FROW + kh + 8];
    }

    // ldmatrix lane base for V (lanes 0-15 supply 16 key-row pointers)
    const uint32_t vLane = smem_u32(Vs) + (uint32_t)((lane & 15) * FROW) * 2;

    float o_[8][4] = {};
    float mrow[2] = {-1e30f, -1e30f}, lrow[2] = {0.f, 0.f};

    const int NIT = SEQ / 64;
    CP_WAIT0();
    __syncthreads();

    for (int it = 0; it < NIT; ++it) {
        const int bf = it & 1;
        if (it + 1 < NIT) {
            const int nb = bf ^ 1;
            const int kt = (it + 1) * 64;
            #pragma unroll
            for (int p = 0; p < 2; ++p) {
                const int idx = t + 256 * p;
                const int row = idx >> 3, ch = (idx & 7) * 8;
                cp16(&Ks[nb * 64 * FROW + row * FROW + ch],
                     k + base + (size_t)(kt + row) * EMBED + ch);
                cp16(&Vs[nb * 64 * FROW + row * FROW + ch],
                     v + base + (size_t)(kt + row) * EMBED + ch);
            }
            CP_COMMIT();
        }
        const __half* Kb = Ks + bf * 64 * FROW;

        // S = Q * K^T : 32 mmas (4 k16-chunks x 8 n-tiles)
        float s[8][4] = {};
        #pragma unroll
        for (int c = 0; c < 4; ++c) {
            const int kh = c * 16 + 2 * e;
            #pragma unroll
            for (int n = 0; n < 8; ++n) {
                uint32_t b0 = *(const uint32_t*)&Kb[(n * 8 + g) * FROW + kh];
                uint32_t b1 = *(const uint32_t*)&Kb[(n * 8 + g) * FROW + kh + 8];
                mma_f16(s[n], qa[c], b0, b1);
            }
        }

        // online softmax per row-half (fp32, base-2)
        #pragma unroll
        for (int hh = 0; hh < 2; ++hh) {
            const int ci = hh * 2;
            float mx = -1e30f;
            #pragma unroll
            for (int n = 0; n < 8; ++n)
                mx = fmaxf(mx, fmaxf(s[n][ci], s[n][ci + 1]));
            mx = fmaxf(mx, __shfl_xor_sync(0xffffffffu, mx, 1));
            mx = fmaxf(mx, __shfl_xor_sync(0xffffffffu, mx, 2));
            const float mn = fmaxf(mrow[hh], mx);
            const float al = ex2(mrow[hh] - mn);
            mrow[hh] = mn;
            float sum = 0.f;
            #pragma unroll
            for (int n = 0; n < 8; ++n) {
                const float p0 = ex2(s[n][ci] - mn);
                const float p1 = ex2(s[n][ci + 1] - mn);
                s[n][ci] = p0; s[n][ci + 1] = p1;
                sum += p0 + p1;
            }
            sum += __shfl_xor_sync(0xffffffffu, sum, 1);
            sum += __shfl_xor_sync(0xffffffffu, sum, 2);
            lrow[hh] = lrow[hh] * al + sum;
            if (al != 1.0f) {
                #pragma unroll
                for (int n = 0; n < 8; ++n) { o_[n][ci] *= al; o_[n][ci + 1] *= al; }
            }
            const int pr = (m0 + g + 8 * hh) * FROW;
            #pragma unroll
            for (int n = 0; n < 8; ++n)
                *(__half2*)&Ps[pr + n * 8 + 2 * e] =
                    __floats2half2_rn(s[n][ci], s[n][ci + 1]);
        }
        __syncwarp();   // Ps rows are per-warp private

        // O += P * V : P plain word loads, V via ldmatrix.trans (one ahead)
        const uint32_t vBase = vLane + (uint32_t)(bf * 64 * FROW) * 2;
        #pragma unroll
        for (int ks = 0; ks < 4; ++ks) {
            const int kh = ks * 16 + 2 * e;
            uint32_t a[4];
            a[0] = *(const uint32_t*)&Ps[(m0 + g) * FROW + kh];
            a[1] = *(const uint32_t*)&Ps[(m0 + g + 8) * FROW + kh];
            a[2] = *(const uint32_t*)&Ps[(m0 + g) * FROW + kh + 8];
            a[3] = *(const uint32_t*)&Ps[(m0 + g + 8) * FROW + kh + 8];
            const uint32_t vRow = vBase + (uint32_t)(ks * 16 * FROW) * 2;
            uint32_t vb0[2], vb1[2];
            ldsm_x2_t(vb0[0], vb1[0], vRow);
            #pragma unroll
            for (int n = 0; n < 8; ++n) {
                if (n < 7) ldsm_x2_t(vb0[(n + 1) & 1], vb1[(n + 1) & 1],
                                     vRow + (n + 1) * 16);
                mma_f16(o_[n], a, vb0[n & 1], vb1[n & 1]);
            }
        }

        CP_WAIT0();
        __syncthreads();   // next tile landed; all readers done with bf
    }

    // epilogue: O /= l, convert fp16, write [B*S, EMBED] at head offset
    #pragma unroll
    for (int hh = 0; hh < 2; ++hh) {
        const float inv = 1.0f / lrow[hh];
        const int row = qrow0 + m0 + g + 8 * hh;
        const int ci = hh * 2;
        #pragma unroll
        for (int n = 0; n < 8; ++n) {
            *(__half2*)(o + base + (size_t)row * EMBED + n * 8 + 2 * e) =
                __floats2half2_rn(o_[n][ci] * inv, o_[n][ci + 1] * inv);
        }
    }
}

// ---------------------------------------------------------------------------
extern "C" void kernel_launch(void* const* d_in, const int* in_sizes, int n_in,
                              void* d_out, int out_size)
{
    const float* x  = (const float*)d_in[0];
    const float* Wq = (const float*)d_in[1];
    const float* bq = (const float*)d_in[2];
    const float* Wk = (const float*)d_in[3];
    const float* bk = (const float*)d_in[4];
    const float* Wv = (const float*)d_in[5];
    const float* bv = (const float*)d_in[6];
    const float* Wo = (const float*)d_in[7];
    const float* bo = (const float*)d_in[8];
    float* out = (float*)d_out;

    __half *xh, *qh, *kh, *vh, *oh, *wth, *woh;
    float *bc;
    cudaGetSymbolAddress((void**)&xh,  g_xh);
    cudaGetSymbolAddress((void**)&qh,  g_qh);
    cudaGetSymbolAddress((void**)&kh,  g_kh);
    cudaGetSymbolAddress((void**)&vh,  g_vh);
    cudaGetSymbolAddress((void**)&oh,  g_oh);
    cudaGetSymbolAddress((void**)&wth, g_wth);
    cudaGetSymbolAddress((void**)&woh, g_woh);
    cudaGetSymbolAddress((void**)&bc,  g_bc);

    const int nx4 = MTOT * EMBED / 4;
    tohalf<<<(nx4 + 255) / 256, 256>>>(x, xh, nx4);
    transpose_half<<<dim3(EMBED / 32, EMBED / 32, 4), 256>>>(Wq, Wk, Wv, Wo, wth, woh);
    bias_cat<<<(3 * EMBED + 255) / 256, 256>>>(bq, bk, bv, bc);

    cudaFuncSetAttribute(gemm_h, cudaFuncAttributeMaxDynamicSharedMemorySize,
                         GEMM_SMEM);
    cudaFuncSetAttribute(flash_h, cudaFuncAttributeMaxDynamicSharedMemorySize,
                         FLASH_SMEM);

    // fused QKV: grid (24, 64) -> fp16 q/k/v
    gemm_h<<<dim3(24, MTOT / 128), 256, GEMM_SMEM>>>(xh, wth, bc, qh, kh, vh, 0);

    flash_h<<<dim3(BATCH * NHEADS, SEQ / 128), 256, FLASH_SMEM>>>(qh, kh, vh, oh);

    // output projection: grid (8, 64) -> fp32 out
    gemm_h<<<dim3(8, MTOT / 128), 256, GEMM_SMEM>>>(oh, woh, bo, out, out, out, 1);
}

// round 17
// speedup vs baseline: 2.8137x; 1.0298x over previous
#include <cuda_runtime.h>
#include <cuda_fp16.h>
#include <cstdint>

#define EMBED 1024
#define NHEADS 16
#define HDIM 64
#define BATCH 4
#define SEQ 2048
#define MTOT (BATCH * SEQ)   // 8192

// q pre-scale: (1/sqrt(64)) * log2(e)  -> softmax computed base-2
#define QSCALE 0.18033688011112042f

// Scratch (static device globals: allowed; no runtime allocation)
__device__ __half g_xh [(size_t)MTOT * EMBED];
__device__ __half g_qh [(size_t)MTOT * EMBED];
__device__ __half g_kh [(size_t)MTOT * EMBED];
__device__ __half g_vh [(size_t)MTOT * EMBED];
__device__ __half g_oh [(size_t)MTOT * EMBED];
__device__ __half g_wth[(size_t)3 * EMBED * EMBED];  // [Wq;Wk;Wv]^T  [N][K]
__device__ __half g_woh[(size_t)EMBED * EMBED];      // Wo^T          [N][K]
__device__ float  g_bc [3 * EMBED];                  // concat bias (q scaled)

// D(16x8,f32) += A(16x16,f16) * B(16x8,f16)
__device__ __forceinline__ void mma_f16(float c[4], const uint32_t a[4],
                                        uint32_t b0, uint32_t b1) {
    asm volatile(
        "mma.sync.aligned.m16n8k16.row.col.f32.f16.f16.f32 "
        "{%0,%1,%2,%3}, {%4,%5,%6,%7}, {%8,%9}, {%0,%1,%2,%3};"
        : "+f"(c[0]), "+f"(c[1]), "+f"(c[2]), "+f"(c[3])
        : "r"(a[0]), "r"(a[1]), "r"(a[2]), "r"(a[3]), "r"(b0), "r"(b1));
}

// four 8x8 b16 tiles; lanes 0-7/8-15/16-23/24-31 give row addrs of m0..m3
__device__ __forceinline__ void ldsm_x4(uint32_t& r0, uint32_t& r1,
                                        uint32_t& r2, uint32_t& r3, uint32_t a) {
    asm volatile("ldmatrix.sync.aligned.m8n8.x4.shared.b16 {%0,%1,%2,%3}, [%4];"
                 : "=r"(r0), "=r"(r1), "=r"(r2), "=r"(r3) : "r"(a));
}

// transposed 8x8 b16 tile pair (b-frags from row-major [k][n] smem)
__device__ __forceinline__ void ldsm_x2_t(uint32_t& r0, uint32_t& r1, uint32_t a) {
    asm volatile("ldmatrix.sync.aligned.m8n8.x2.trans.shared.b16 {%0,%1}, [%2];"
                 : "=r"(r0), "=r"(r1) : "r"(a));
}

__device__ __forceinline__ void cp16(void* dst_smem, const void* src) {
    uint32_t d = (uint32_t)__cvta_generic_to_shared(dst_smem);
    asm volatile("cp.async.cg.shared.global [%0], [%1], 16;" :: "r"(d), "l"(src));
}
#define CP_COMMIT() asm volatile("cp.async.commit_group;")
#define CP_WAIT0()  asm volatile("cp.async.wait_group 0;" ::: "memory")

__device__ __forceinline__ uint32_t smem_u32(const void* p) {
    return (uint32_t)__cvta_generic_to_shared(p);
}
__device__ __forceinline__ float ex2(float x) {
    float r;
    asm("ex2.approx.f32 %0, %1;" : "=f"(r) : "f"(x));
    return r;
}

// ---------------------------------------------------------------------------
// fp32 -> fp16 elementwise (for x)
// ---------------------------------------------------------------------------
__global__ void tohalf(const float* __restrict__ s, __half* __restrict__ d, int n4)
{
    int i = blockIdx.x * 256 + threadIdx.x;
    if (i < n4) {
        float4 v = ((const float4*)s)[i];
        ((__half2*)d)[2 * i]     = __floats2half2_rn(v.x, v.y);
        ((__half2*)d)[2 * i + 1] = __floats2half2_rn(v.z, v.w);
    }
}

// ---------------------------------------------------------------------------
// all 4 weight transposes -> fp16 in one launch (z picks matrix); Wq * QSCALE
// ---------------------------------------------------------------------------
__global__ __launch_bounds__(256) void transpose_half(
    const float* __restrict__ Wq, const float* __restrict__ Wk,
    const float* __restrict__ Wv, const float* __restrict__ Wo,
    __half* __restrict__ wt, __half* __restrict__ wo)
{
    __shared__ float tl[32][33];
    const int z = blockIdx.z;
    const float* src = (z == 0) ? Wq : (z == 1) ? Wk : (z == 2) ? Wv : Wo;
    __half* dst = (z == 3) ? wo : wt + (size_t)z * EMBED * EMBED;
    const float sc = (z == 0) ? QSCALE : 1.0f;

    const int tx = threadIdx.x & 31, ty = threadIdx.x >> 5;  // 32 x 8
    const int x0 = blockIdx.x * 32, y0 = blockIdx.y * 32;
    #pragma unroll
    for (int j = 0; j < 32; j += 8)
        tl[ty + j][tx] = src[(size_t)(y0 + ty + j) * EMBED + x0 + tx] * sc;
    __syncthreads();
    #pragma unroll
    for (int j = 0; j < 32; j += 8)
        dst[(size_t)(x0 + ty + j) * EMBED + y0 + tx] = __float2half_rn(tl[tx][ty + j]);
}

// bias concat: bc[0:1024)=bq*QSCALE, [1024:2048)=bk, [2048:3072)=bv
__global__ void bias_cat(const float* __restrict__ bq, const float* __restrict__ bk,
                         const float* __restrict__ bv, float* __restrict__ bc)
{
    int i = blockIdx.x * 256 + threadIdx.x;
    if (i < EMBED)          bc[i] = bq[i] * QSCALE;
    else if (i < 2 * EMBED) bc[i] = bk[i - EMBED];
    else if (i < 3 * EMBED) bc[i] = bv[i - 2 * EMBED];
}

// ---------------------------------------------------------------------------
// fp16 mma.sync GEMM (m16n8k16): block 128x128, 8 warps (4M x 2N),
// warp tile 32x64, BK=64 halves (4 k16 steps), 2-stage cp.async, 2 CTAs/SM.
// ALL fragment loads via ldmatrix.x4 (6 per ks-step vs 24 scalar LDS).
// Tiles [row][k] halves, row stride 72 (36 words = 4 mod 32: each 8x8
// ldmatrix phase reads banks 4r..4r+3, all 32 distinct -> conflict-free).
// fp32out=0: route fp16 output to Q/K/V by n-block;  fp32out=1: final fp32.
// smem: 2 x (A 128x72 + B 128x72) halves = 73728 B
// ---------------------------------------------------------------------------
#define GPADH 72
#define GTILEB (128 * GPADH * 2)
#define GEMM_SMEM (2 * 2 * 128 * GPADH * 2)

__global__ __launch_bounds__(256, 2) void gemm_h(
    const __half* __restrict__ A, const __half* __restrict__ BT,
    const float* __restrict__ bias, void* P0, void* P1, void* P2, int fp32out)
{
    extern __shared__ __half shh[];
    __half* As = shh;                       // [2][128][72]
    __half* Bs = shh + 2 * 128 * GPADH;     // [2][128][72]

    const int t = threadIdx.x;
    const int lane = t & 31, warp = t >> 5;
    const int g = lane >> 2, e = lane & 3;
    const int m0 = (warp & 3) * 32, n0 = (warp >> 2) * 64;

    const int row0 = blockIdx.y * 128;
    const int bx = blockIdx.x;
    const int id = bx >> 3;                       // output matrix (qkv mode)
    const int col0 = (bx & 7) * 128;              // col within matrix

    // loaders: thread covers (row = t>>3 (+32p), 16B chunk = t&7)
    const int lr = t >> 3, lc = (t & 7) * 8;      // lc in halves
    const __half* Ab = A  + (size_t)(row0 + lr) * EMBED + lc;
    const __half* Bb = BT + (size_t)(bx * 128 + lr) * EMBED + lc;

    // ldmatrix lane addressing: row = lane&15, k-col = (lane>>4)*8
    const int lrow = lane & 15, lcol = (lane >> 4) * 8;
    const uint32_t aB = smem_u32(As) + (uint32_t)(((m0 + lrow) * GPADH + lcol) * 2);
    const uint32_t bB = smem_u32(Bs) + (uint32_t)(((n0 + lrow) * GPADH + lcol) * 2);

    #define GREFILL(k0, buf) do {                                              \
        __half* sA = As + (buf) * 128 * GPADH;                                 \
        __half* sB = Bs + (buf) * 128 * GPADH;                                 \
        _Pragma("unroll")                                                      \
        for (int p = 0; p < 4; ++p) {                                          \
            cp16(&sA[(lr + 32 * p) * GPADH + lc], Ab + (size_t)(32 * p) * EMBED + (k0)); \
            cp16(&sB[(lr + 32 * p) * GPADH + lc], Bb + (size_t)(32 * p) * EMBED + (k0)); \
        }                                                                      \
        CP_COMMIT();                                                           \
    } while (0)

    GREFILL(0, 0);

    float acc[2][8][4] = {};
    const int NIT = EMBED / 64;     // 16

    for (int it = 0; it < NIT; ++it) {
        CP_WAIT0();
        __syncthreads();
        if (it + 1 < NIT) GREFILL((it + 1) * 64, (it + 1) & 1);

        const uint32_t aA = aB + (it & 1) * GTILEB;
        const uint32_t bA = bB + (it & 1) * GTILEB;

        #pragma unroll
        for (int ks = 0; ks < 4; ++ks) {
            uint32_t a[2][4];
            ldsm_x4(a[0][0], a[0][1], a[0][2], a[0][3], aA + ks * 32);
            ldsm_x4(a[1][0], a[1][1], a[1][2], a[1][3],
                    aA + 16 * GPADH * 2 + ks * 32);
            #pragma unroll
            for (int np = 0; np < 4; ++np) {
                uint32_t b0a, b0b, b1a, b1b;
                ldsm_x4(b0a, b0b, b1a, b1b, bA + np * 16 * GPADH * 2 + ks * 32);
                mma_f16(acc[0][2 * np],     a[0], b0a, b1a);
                mma_f16(acc[1][2 * np],     a[1], b0a, b1a);
                mma_f16(acc[0][2 * np + 1], a[0], b0b, b1b);
                mma_f16(acc[1][2 * np + 1], a[1], b0b, b1b);
            }
        }
    }

    // epilogue
    #pragma unroll
    for (int mt = 0; mt < 2; ++mt) {
        const int r = row0 + m0 + mt * 16 + g;
        #pragma unroll
        for (int n = 0; n < 8; ++n) {
            const int cl = col0 + n0 + n * 8 + 2 * e;         // col in matrix
            const int cb = bx * 128 + n0 + n * 8 + 2 * e;     // col in bias buf
            const float b0 = bias[cb], b1 = bias[cb + 1];
            const float v00 = acc[mt][n][0] + b0, v01 = acc[mt][n][1] + b1;
            const float v10 = acc[mt][n][2] + b0, v11 = acc[mt][n][3] + b1;
            if (fp32out) {
                float* D = (float*)P0;
                *(float2*)&D[(size_t)r * EMBED + cl]       = make_float2(v00, v01);
                *(float2*)&D[(size_t)(r + 8) * EMBED + cl] = make_float2(v10, v11);
            } else {
                __half* D = (__half*)((id == 0) ? P0 : (id == 1) ? P1 : P2);
                *(__half2*)&D[(size_t)r * EMBED + cl]       = __floats2half2_rn(v00, v01);
                *(__half2*)&D[(size_t)(r + 8) * EMBED + cl] = __floats2half2_rn(v10, v11);
            }
        }
    }
}

// ---------------------------------------------------------------------------
// Flash attention fp16 (m16n8k16): Q-block 128 rows, 8 warps x 16 rows,
// Bc=64, 2-stage cp.async K/V, 2 CTAs/SM.  Base-2 softmax (ex2.approx).
// Q/K/P fragments via ldmatrix.x4; V via ldmatrix.x2.trans.
// smem (halves): Ks[2][64][72] Vs[2][64][72] Ps[128][72] = 55296 B
// ---------------------------------------------------------------------------
#define FROW 72                         // halves per smem row
#define FKS_OFF 0
#define FVS_OFF (2 * 64 * FROW)
#define FPS_OFF (FVS_OFF + 2 * 64 * FROW)
#define FLASH_SMEM ((FPS_OFF + 128 * FROW) * 2)

__global__ __launch_bounds__(256, 2) void flash_h(
    const __half* __restrict__ q, const __half* __restrict__ k,
    const __half* __restrict__ v, __half* __restrict__ o)
{
    extern __shared__ __half shf[];
    __half* Ks = shf + FKS_OFF;
    __half* Vs = shf + FVS_OFF;
    __half* Ps = shf + FPS_OFF;

    const int t = threadIdx.x;
    const int lane = t & 31, warp = t >> 5;
    const int g = lane >> 2, e = lane & 3;
    const int m0 = warp * 16;

    const int bh = blockIdx.x;
    const int b = bh >> 4, h = bh & 15;
    const int qrow0 = blockIdx.y * 128;
    const size_t base = ((size_t)b * SEQ) * EMBED + (size_t)h * HDIM;

    // prefetch K/V tile 0 into buf 0 (idx -> row = idx>>3, 16B chunk = idx&7)
    #pragma unroll
    for (int p = 0; p < 2; ++p) {
        const int idx = t + 256 * p;
        const int row = idx >> 3, ch = (idx & 7) * 8;
        cp16(&Ks[row * FROW + ch], k + base + (size_t)row * EMBED + ch);
        cp16(&Vs[row * FROW + ch], v + base + (size_t)row * EMBED + ch);
    }
    CP_COMMIT();

    // stage Q (128 x 64 halves) into Ps
    #pragma unroll
    for (int i = 0; i < 4; ++i) {
        const int idx = t + 256 * i;
        const int row = idx >> 3, ch = (idx & 7) * 8;
        *(uint4*)&Ps[row * FROW + ch] =
            *(const uint4*)(q + base + (size_t)(qrow0 + row) * EMBED + ch);
    }
    __syncthreads();

    // ldmatrix lane addressing
    const int lrow = lane & 15, lcol = (lane >> 4) * 8;
    const uint32_t pLd = smem_u32(Ps) + (uint32_t)(((m0 + lrow) * FROW + lcol) * 2);
    const uint32_t kLd = smem_u32(Ks) + (uint32_t)((lrow * FROW + lcol) * 2);
    const uint32_t vLane = smem_u32(Vs) + (uint32_t)((lane & 15) * FROW) * 2;

    // hoist Q fragments via ldmatrix
    uint32_t qa[4][4];
    #pragma unroll
    for (int c = 0; c < 4; ++c)
        ldsm_x4(qa[c][0], qa[c][1], qa[c][2], qa[c][3], pLd + c * 32);

    float o_[8][4] = {};
    float mrow[2] = {-1e30f, -1e30f}, lrow2[2] = {0.f, 0.f};

    const int NIT = SEQ / 64;
    CP_WAIT0();
    __syncthreads();

    for (int it = 0; it < NIT; ++it) {
        const int bf = it & 1;
        if (it + 1 < NIT) {
            const int nb = bf ^ 1;
            const int kt = (it + 1) * 64;
            #pragma unroll
            for (int p = 0; p < 2; ++p) {
                const int idx = t + 256 * p;
                const int row = idx >> 3, ch = (idx & 7) * 8;
                cp16(&Ks[nb * 64 * FROW + row * FROW + ch],
                     k + base + (size_t)(kt + row) * EMBED + ch);
                cp16(&Vs[nb * 64 * FROW + row * FROW + ch],
                     v + base + (size_t)(kt + row) * EMBED + ch);
            }
            CP_COMMIT();
        }
        const uint32_t kA = kLd + (uint32_t)(bf * 64 * FROW) * 2;

        // S = Q * K^T : K b-frags via ldmatrix.x4 (4 per c-step)
        float s[8][4] = {};
        #pragma unroll
        for (int c = 0; c < 4; ++c) {
            #pragma unroll
            for (int np = 0; np < 4; ++np) {
                uint32_t b0a, b0b, b1a, b1b;
                ldsm_x4(b0a, b0b, b1a, b1b, kA + np * 16 * FROW * 2 + c * 32);
                mma_f16(s[2 * np],     qa[c], b0a, b1a);
                mma_f16(s[2 * np + 1], qa[c], b0b, b1b);
            }
        }

        // online softmax per row-half (fp32, base-2)
        #pragma unroll
        for (int hh = 0; hh < 2; ++hh) {
            const int ci = hh * 2;
            float mx = -1e30f;
            #pragma unroll
            for (int n = 0; n < 8; ++n)
                mx = fmaxf(mx, fmaxf(s[n][ci], s[n][ci + 1]));
            mx = fmaxf(mx, __shfl_xor_sync(0xffffffffu, mx, 1));
            mx = fmaxf(mx, __shfl_xor_sync(0xffffffffu, mx, 2));
            const float mn = fmaxf(mrow[hh], mx);
            const float al = ex2(mrow[hh] - mn);
            mrow[hh] = mn;
            float sum = 0.f;
            #pragma unroll
            for (int n = 0; n < 8; ++n) {
                const float p0 = ex2(s[n][ci] - mn);
                const float p1 = ex2(s[n][ci + 1] - mn);
                s[n][ci] = p0; s[n][ci + 1] = p1;
                sum += p0 + p1;
            }
            sum += __shfl_xor_sync(0xffffffffu, sum, 1);
            sum += __shfl_xor_sync(0xffffffffu, sum, 2);
            lrow2[hh] = lrow2[hh] * al + sum;
            if (al != 1.0f) {
                #pragma unroll
                for (int n = 0; n < 8; ++n) { o_[n][ci] *= al; o_[n][ci + 1] *= al; }
            }
            const int pr = (m0 + g + 8 * hh) * FROW;
            #pragma unroll
            for (int n = 0; n < 8; ++n)
                *(__half2*)&Ps[pr + n * 8 + 2 * e] =
                    __floats2half2_rn(s[n][ci], s[n][ci + 1]);
        }
        __syncwarp();   // Ps rows are per-warp private

        // O += P * V : P a-frags via ldmatrix.x4, V via ldmatrix.trans
        const uint32_t vBase = vLane + (uint32_t)(bf * 64 * FROW) * 2;
        #pragma unroll
        for (int ks = 0; ks < 4; ++ks) {
            uint32_t a[4];
            ldsm_x4(a[0], a[1], a[2], a[3], pLd + ks * 32);
            const uint32_t vRow = vBase + (uint32_t)(ks * 16 * FROW) * 2;
            uint32_t vb0[2], vb1[2];
            ldsm_x2_t(vb0[0], vb1[0], vRow);
            #pragma unroll
            for (int n = 0; n < 8; ++n) {
                if (n < 7) ldsm_x2_t(vb0[(n + 1) & 1], vb1[(n + 1) & 1],
                                     vRow + (n + 1) * 16);
                mma_f16(o_[n], a, vb0[n & 1], vb1[n & 1]);
            }
        }

        CP_WAIT0();
        __syncthreads();   // next tile landed; all readers done with bf
    }

    // epilogue: O /= l, convert fp16, write [B*S, EMBED] at head offset
    #pragma unroll
    for (int hh = 0; hh < 2; ++hh) {
        const float inv = 1.0f / lrow2[hh];
        const int row = qrow0 + m0 + g + 8 * hh;
        const int ci = hh * 2;
        #pragma unroll
        for (int n = 0; n < 8; ++n) {
            *(__half2*)(o + base + (size_t)row * EMBED + n * 8 + 2 * e) =
                __floats2half2_rn(o_[n][ci] * inv, o_[n][ci + 1] * inv);
        }
    }
}

// ---------------------------------------------------------------------------
extern "C" void kernel_launch(void* const* d_in, const int* in_sizes, int n_in,
                              void* d_out, int out_size)
{
    const float* x  = (const float*)d_in[0];
    const float* Wq = (const float*)d_in[1];
    const float* bq = (const float*)d_in[2];
    const float* Wk = (const float*)d_in[3];
    const float* bk = (const float*)d_in[4];
    const float* Wv = (const float*)d_in[5];
    const float* bv = (const float*)d_in[6];
    const float* Wo = (const float*)d_in[7];
    const float* bo = (const float*)d_in[8];
    float* out = (float*)d_out;

    __half *xh, *qh, *kh, *vh, *oh, *wth, *woh;
    float *bc;
    cudaGetSymbolAddress((void**)&xh,  g_xh);
    cudaGetSymbolAddress((void**)&qh,  g_qh);
    cudaGetSymbolAddress((void**)&kh,  g_kh);
    cudaGetSymbolAddress((void**)&vh,  g_vh);
    cudaGetSymbolAddress((void**)&oh,  g_oh);
    cudaGetSymbolAddress((void**)&wth, g_wth);
    cudaGetSymbolAddress((void**)&woh, g_woh);
    cudaGetSymbolAddress((void**)&bc,  g_bc);

    const int nx4 = MTOT * EMBED / 4;
    tohalf<<<(nx4 + 255) / 256, 256>>>(x, xh, nx4);
    transpose_half<<<dim3(EMBED / 32, EMBED / 32, 4), 256>>>(Wq, Wk, Wv, Wo, wth, woh);
    bias_cat<<<(3 * EMBED + 255) / 256, 256>>>(bq, bk, bv, bc);

    cudaFuncSetAttribute(gemm_h, cudaFuncAttributeMaxDynamicSharedMemorySize,
                         GEMM_SMEM);
    cudaFuncSetAttribute(flash_h, cudaFuncAttributeMaxDynamicSharedMemorySize,
                         FLASH_SMEM);

    // fused QKV: grid (24, 64) -> fp16 q/k/v
    gemm_h<<<dim3(24, MTOT / 128), 256, GEMM_SMEM>>>(xh, wth, bc, qh, kh, vh, 0);

    flash_h<<<dim3(BATCH * NHEADS, SEQ / 128), 256, FLASH_SMEM>>>(qh, kh, vh, oh);

    // output projection: grid (8, 64) -> fp32 out
    gemm_h<<<dim3(8, MTOT / 128), 256, GEMM_SMEM>>>(oh, woh, bo, out, out, out, 1);
}